// round 10
// baseline (speedup 1.0000x reference)
#include <cuda_runtime.h>
#include <cuda_bf16.h>
#include <math.h>
#include <stdint.h>

#define BB 2
#define TT 2048
#define CC 1024
#define HH 16
#define HD 64
#define C3 3072

__device__ float g_qkv[(size_t)BB * TT * C3];   // 4096 x 3072
__device__ float g_attn[(size_t)BB * TT * CC];  // 4096 x 1024

// ---------------------------------------------------------------------------
// mma / ldmatrix helpers
// ---------------------------------------------------------------------------
__device__ __forceinline__ void mma_bf16(float* c, const unsigned* a, const unsigned* b) {
    asm("mma.sync.aligned.m16n8k16.row.col.f32.bf16.bf16.f32 "
        "{%0,%1,%2,%3},{%4,%5,%6,%7},{%8,%9},{%0,%1,%2,%3};"
        : "+f"(c[0]), "+f"(c[1]), "+f"(c[2]), "+f"(c[3])
        : "r"(a[0]), "r"(a[1]), "r"(a[2]), "r"(a[3]), "r"(b[0]), "r"(b[1]));
}
__device__ __forceinline__ void ldm_x4(unsigned* r, uint32_t addr) {
    asm volatile("ldmatrix.sync.aligned.m8n8.x4.shared.b16 {%0,%1,%2,%3}, [%4];"
                 : "=r"(r[0]), "=r"(r[1]), "=r"(r[2]), "=r"(r[3]) : "r"(addr));
}
__device__ __forceinline__ void ldm_x4t(unsigned* r, uint32_t addr) {
    asm volatile("ldmatrix.sync.aligned.m8n8.x4.trans.shared.b16 {%0,%1,%2,%3}, [%4];"
                 : "=r"(r[0]), "=r"(r[1]), "=r"(r[2]), "=r"(r[3]) : "r"(addr));
}

__device__ __forceinline__ unsigned pack2bf(float lo, float hi) {
    unsigned r;
    asm("cvt.rn.bf16x2.f32 %0, %1, %2;" : "=r"(r) : "f"(hi), "f"(lo));
    return r;
}
__device__ __forceinline__ float bflo(unsigned u) { return __uint_as_float(u << 16); }
__device__ __forceinline__ float bfhi(unsigned u) { return __uint_as_float(u & 0xffff0000u); }

// fast exp on fma/alu pipes (no MUFU)
__device__ __forceinline__ float fexp(float x) {
    float y = x * 1.4426950408889634f;
    y = fmaxf(y, -126.0f);
    int ni = __float2int_rd(y);
    float f = y - (float)ni;
    float p = 0.0018775767f;
    p = fmaf(p, f, 0.0089893397f);
    p = fmaf(p, f, 0.0558282185f);
    p = fmaf(p, f, 0.2400789568f);
    p = fmaf(p, f, 0.6931531203f);
    p = fmaf(p, f, 0.9999999702f);
    return __uint_as_float(__float_as_uint(p) + ((unsigned)ni << 23));
}

__device__ __forceinline__ void split4(float4 v, uint2& hp, uint2& lp) {
    unsigned h01 = pack2bf(v.x, v.y);
    unsigned h23 = pack2bf(v.z, v.w);
    float r0 = v.x - bflo(h01);
    float r1 = v.y - bfhi(h01);
    float r2 = v.z - bflo(h23);
    float r3 = v.w - bfhi(h23);
    hp = make_uint2(h01, h23);
    lp = make_uint2(pack2bf(r0, r1), pack2bf(r2, r3));
}

// ---------------------------------------------------------------------------
// Tensor-core GEMM (NT), bf16 3-term split.
// CTA 128x128, BK=16, 256 threads (8 warps, 2x4), warp tile 64x32.
// 2 CTAs/SM so one CTA's mma covers the other's convert/sync bubbles.
// ---------------------------------------------------------------------------
#define GP 24
#define A_H (128 * GP)                  // 3072 halves
#define B_H (128 * GP)                  // 3072 halves
#define STAGE_H (2 * A_H + 2 * B_H)     // 12288 halves
#define GEMM_SMEM_BYTES (2 * STAGE_H * 2)   // 49152 B

__device__ __forceinline__ void cvt_store(unsigned short* hi_t, unsigned short* lo_t,
                                          int row, int col, float4 v) {
    uint2 hp, lp;
    split4(v, hp, lp);
    *(uint2*)&hi_t[row * GP + col] = hp;
    *(uint2*)&lo_t[row * GP + col] = lp;
}

__global__ __launch_bounds__(256, 2) void gemm_bf16x3(
    const float* __restrict__ A, const float* __restrict__ W,
    float* __restrict__ Cout, int M, int N, int K)
{
    extern __shared__ unsigned short sh[];

    const int tid = threadIdx.x;
    const int wid = tid >> 5;
    const int lane = tid & 31;
    const int warp_m = wid >> 2;        // 0..1 -> 64-row slices of 128
    const int warp_n = wid & 3;         // 0..3 -> 32-col slices of 128

    const float* Ap = A + (size_t)blockIdx.y * 128 * K;
    const float* Wp = W + (size_t)blockIdx.x * 128 * K;

    // 512 float4 slots per tile (128 rows x 4 chunks); thread covers rows r0, r0+64
    const int r0 = tid >> 2;
    const int c0 = (tid & 3) * 4;

    const uint32_t smem_u32 = (uint32_t)__cvta_generic_to_shared(sh);

    const int a_lrow = (lane & 7) + ((lane >> 3) & 1) * 8;
    const int a_lcol = ((lane >> 4) & 1) * 8;

    float acc[4][4][4];
#pragma unroll
    for (int i = 0; i < 4; i++)
#pragma unroll
        for (int j = 0; j < 4; j++)
#pragma unroll
            for (int q = 0; q < 4; q++) acc[i][j][q] = 0.f;

    const int nstage = K / 16;

    float4 va0 = *(const float4*)(Ap + (size_t)r0 * K + c0);
    float4 va1 = *(const float4*)(Ap + (size_t)(r0 + 64) * K + c0);
    float4 vb0 = *(const float4*)(Wp + (size_t)r0 * K + c0);
    float4 vb1 = *(const float4*)(Wp + (size_t)(r0 + 64) * K + c0);
    cvt_store(sh,           sh + A_H,           r0,      c0, va0);
    cvt_store(sh,           sh + A_H,           r0 + 64, c0, va1);
    cvt_store(sh + 2 * A_H, sh + 2 * A_H + B_H, r0,      c0, vb0);
    cvt_store(sh + 2 * A_H, sh + 2 * A_H + B_H, r0 + 64, c0, vb1);
    __syncthreads();

    for (int s = 0; s < nstage; s++) {
        if (s + 1 < nstage) {
            const int k0 = (s + 1) * 16;
            va0 = *(const float4*)(Ap + (size_t)r0 * K + k0 + c0);
            va1 = *(const float4*)(Ap + (size_t)(r0 + 64) * K + k0 + c0);
            vb0 = *(const float4*)(Wp + (size_t)r0 * K + k0 + c0);
            vb1 = *(const float4*)(Wp + (size_t)(r0 + 64) * K + k0 + c0);
        }
        {
            const uint32_t base = smem_u32 + (unsigned)(s & 1) * (STAGE_H * 2);
            const uint32_t baseAhi = base;
            const uint32_t baseAlo = base + A_H * 2;
            const uint32_t baseBhi = base + 2 * A_H * 2;
            const uint32_t baseBlo = base + (2 * A_H + B_H) * 2;

            // hold all B fragments (x4: two n-blocks per load)
            unsigned Bh[2][4], Bl[2][4];
#pragma unroll
            for (int anp = 0; anp < 2; anp++) {
                const uint32_t off = (uint32_t)(((warp_n * 32 + anp * 16 +
                                                  ((lane >> 4) & 1) * 8 + (lane & 7)) * GP +
                                                 ((lane >> 3) & 1) * 8) * 2);
                ldm_x4(Bh[anp], baseBhi + off);
                ldm_x4(Bl[anp], baseBlo + off);
            }
#pragma unroll
            for (int am = 0; am < 4; am++) {
                unsigned Ah[4], Al[4];
                const uint32_t off =
                    (uint32_t)(((warp_m * 64 + am * 16 + a_lrow) * GP + a_lcol) * 2);
                ldm_x4(Ah, baseAhi + off);
                ldm_x4(Al, baseAlo + off);
#pragma unroll
                for (int anp = 0; anp < 2; anp++) {
                    mma_bf16(acc[am][2 * anp],     Ah, &Bh[anp][0]);
                    mma_bf16(acc[am][2 * anp + 1], Ah, &Bh[anp][2]);
                    mma_bf16(acc[am][2 * anp],     Ah, &Bl[anp][0]);
                    mma_bf16(acc[am][2 * anp + 1], Ah, &Bl[anp][2]);
                    mma_bf16(acc[am][2 * anp],     Al, &Bh[anp][0]);
                    mma_bf16(acc[am][2 * anp + 1], Al, &Bh[anp][2]);
                }
            }
        }
        if (s + 1 < nstage) {
            unsigned short* st = sh + (unsigned)((s + 1) & 1) * STAGE_H;
            cvt_store(st,           st + A_H,           r0,      c0, va0);
            cvt_store(st,           st + A_H,           r0 + 64, c0, va1);
            cvt_store(st + 2 * A_H, st + 2 * A_H + B_H, r0,      c0, vb0);
            cvt_store(st + 2 * A_H, st + 2 * A_H + B_H, r0 + 64, c0, vb1);
            __syncthreads();
        }
    }

    const int mbase = blockIdx.y * 128 + warp_m * 64 + (lane >> 2);
    const int nbase = blockIdx.x * 128 + warp_n * 32 + (lane & 3) * 2;
#pragma unroll
    for (int am = 0; am < 4; am++) {
#pragma unroll
        for (int an = 0; an < 4; an++) {
            const int r = mbase + am * 16;
            const int c = nbase + an * 8;
            *(float2*)&Cout[(size_t)r * N + c]       = make_float2(acc[am][an][0], acc[am][an][1]);
            *(float2*)&Cout[(size_t)(r + 8) * N + c] = make_float2(acc[am][an][2], acc[am][an][3]);
        }
    }
}

// ---------------------------------------------------------------------------
// RoPE: in-place on q and k slices of g_qkv.
// ---------------------------------------------------------------------------
__global__ void rope_kernel()
{
    int i = blockIdx.x * blockDim.x + threadIdx.x;
    const int total = BB * TT * HH * (HD / 2);
    if (i >= total) return;

    int n = i >> 9;
    int r = i & 511;
    int h = r >> 5;
    int j = r & 31;
    int t = n & (TT - 1);

    float inv_freq = (float)exp(-(double)j * 0.28782313662425575);
    float f = (float)t * inv_freq;
    float c = cosf(f);
    float s = sinf(f);

    float* p = g_qkv + (size_t)n * C3 + h * HD + 2 * j;
    float qr = p[0], qi = p[1];
    p[0] = qr * c - qi * s;
    p[1] = qr * s + qi * c;

    float* pk = p + CC;
    float kr = pk[0], ki = pk[1];
    pk[0] = kr * c - ki * s;
    pk[1] = kr * s + ki * c;
}

// ---------------------------------------------------------------------------
// Tensor-core causal flash attention.
// CTA: 128 q-rows, 8 warps (16 rows/warp), 64-key tiles, dynamic smem.
// 2 CTAs/SM (73.7KB x 2 = 147KB smem, regs capped at 128).
// ---------------------------------------------------------------------------
#define GP2 72
#define KHI_O 0
#define KLO_O 4608
#define VHI_O 9216
#define VLO_O 13824
#define QHI_O 18432
#define QLO_O 27648
#define ATTN_SMEM_HALVES 36864
#define ATTN_SMEM_BYTES (ATTN_SMEM_HALVES * 2)   // 73728 B

__global__ __launch_bounds__(256, 2) void attn_mma()
{
    extern __shared__ unsigned short ash[];

    const int bh = blockIdx.y;
    const int b = bh >> 4;
    const int h = bh & 15;
    const int qtile = 15 - blockIdx.x;     // heavy tiles first
    const int q0 = qtile * 128;
    const int tid = threadIdx.x;
    const int wid = tid >> 5;
    const int lane = tid & 31;
    const float scale = 0.125f;

    const float* base = g_qkv + (size_t)b * TT * C3;

    const uint32_t sm_u = (uint32_t)__cvta_generic_to_shared(ash);
    const uint32_t kh_u = sm_u + KHI_O * 2;
    const uint32_t kl_u = sm_u + KLO_O * 2;
    const uint32_t vh_u = sm_u + VHI_O * 2;
    const uint32_t vl_u = sm_u + VLO_O * 2;
    const uint32_t qh_u = sm_u + QHI_O * 2;
    const uint32_t ql_u = sm_u + QLO_O * 2;

    const int a_lrow = (lane & 7) + ((lane >> 3) & 1) * 8;
    const int a_lcol = ((lane >> 4) & 1) * 8;

    // ---- stage Q (128 x 64) ----
#pragma unroll
    for (int it = 0; it < 8; it++) {
        int idx = tid + it * 256;               // 2048 float4 slots
        int r = idx >> 4, c4 = (idx & 15) * 4;
        float4 v = *(const float4*)(base + (size_t)(q0 + r) * C3 + h * HD + c4);
        uint2 hp, lp;
        split4(v, hp, lp);
        *(uint2*)&ash[QHI_O + r * GP2 + c4] = hp;
        *(uint2*)&ash[QLO_O + r * GP2 + c4] = lp;
    }
    __syncthreads();

    unsigned Qh[4][4], Ql[4][4];
#pragma unroll
    for (int kk = 0; kk < 4; kk++) {
        uint32_t off = (uint32_t)(((wid * 16 + a_lrow) * GP2 + kk * 16 + a_lcol) * 2);
        ldm_x4(Qh[kk], qh_u + off);
        ldm_x4(Ql[kk], ql_u + off);
    }

    float o[8][4];
#pragma unroll
    for (int nb = 0; nb < 8; nb++)
#pragma unroll
        for (int e = 0; e < 4; e++) o[nb][e] = 0.f;
    float m0 = -1e30f, m1 = -1e30f, l0 = 0.f, l1 = 0.f;

    const int rg0 = q0 + wid * 16 + (lane >> 2);
    const int rg1 = rg0 + 8;
    const int cbase = (lane & 3) * 2;

    const int nkt = 2 * qtile + 2;
    for (int kt = 0; kt < nkt; kt++) {
        const int k0 = kt * 64;
        __syncthreads();

        // ---- load K,V tile (64 x 64), split bf16 hi/lo ----
#pragma unroll
        for (int it = 0; it < 4; it++) {
            int idx = tid + it * 256;            // 1024 slots
            int r = idx >> 4, c4 = (idx & 15) * 4;
            const float* src = base + (size_t)(k0 + r) * C3 + CC + h * HD + c4;
            float4 kv = *(const float4*)src;
            float4 vv = *(const float4*)(src + CC);
            uint2 hp, lp;
            split4(kv, hp, lp);
            *(uint2*)&ash[KHI_O + r * GP2 + c4] = hp;
            *(uint2*)&ash[KLO_O + r * GP2 + c4] = lp;
            split4(vv, hp, lp);
            *(uint2*)&ash[VHI_O + r * GP2 + c4] = hp;
            *(uint2*)&ash[VLO_O + r * GP2 + c4] = lp;
        }
        __syncthreads();

        // ---- S = Q K^T (3-pass split, x4 B loads) ----
        float s[8][4];
#pragma unroll
        for (int nb = 0; nb < 8; nb++)
#pragma unroll
            for (int e = 0; e < 4; e++) s[nb][e] = 0.f;

#pragma unroll
        for (int kk = 0; kk < 4; kk++) {
#pragma unroll
            for (int nbp = 0; nbp < 4; nbp++) {
                unsigned Bh[4], Bl[4];
                uint32_t off = (uint32_t)(((nbp * 16 + ((lane >> 4) & 1) * 8 + (lane & 7)) * GP2 +
                                           kk * 16 + ((lane >> 3) & 1) * 8) * 2);
                ldm_x4(Bh, kh_u + off);
                ldm_x4(Bl, kl_u + off);
                mma_bf16(s[2 * nbp],     Qh[kk], &Bh[0]);
                mma_bf16(s[2 * nbp + 1], Qh[kk], &Bh[2]);
                mma_bf16(s[2 * nbp],     Qh[kk], &Bl[0]);
                mma_bf16(s[2 * nbp + 1], Qh[kk], &Bl[2]);
                mma_bf16(s[2 * nbp],     Ql[kk], &Bh[0]);
                mma_bf16(s[2 * nbp + 1], Ql[kk], &Bh[2]);
            }
        }

        // ---- scale + causal mask ----
        const bool diag = (kt >= 2 * qtile);
#pragma unroll
        for (int nb = 0; nb < 8; nb++) {
            int c0g = k0 + nb * 8 + cbase;
#pragma unroll
            for (int e = 0; e < 4; e++) {
                int col = c0g + (e & 1);
                int row = (e < 2) ? rg0 : rg1;
                float v = s[nb][e] * scale;
                if (diag && col > row) v = -1e30f;
                s[nb][e] = v;
            }
        }

        // ---- online softmax ----
        float mx0 = -1e30f, mx1 = -1e30f;
#pragma unroll
        for (int nb = 0; nb < 8; nb++) {
            mx0 = fmaxf(mx0, fmaxf(s[nb][0], s[nb][1]));
            mx1 = fmaxf(mx1, fmaxf(s[nb][2], s[nb][3]));
        }
        mx0 = fmaxf(mx0, __shfl_xor_sync(0xffffffffu, mx0, 1));
        mx0 = fmaxf(mx0, __shfl_xor_sync(0xffffffffu, mx0, 2));
        mx1 = fmaxf(mx1, __shfl_xor_sync(0xffffffffu, mx1, 1));
        mx1 = fmaxf(mx1, __shfl_xor_sync(0xffffffffu, mx1, 2));

        float nm0 = fmaxf(m0, mx0), nm1 = fmaxf(m1, mx1);
        float corr0 = fexp(m0 - nm0), corr1 = fexp(m1 - nm1);
        m0 = nm0; m1 = nm1;

        float ls0 = 0.f, ls1 = 0.f;
#pragma unroll
        for (int nb = 0; nb < 8; nb++) {
            s[nb][0] = fexp(s[nb][0] - nm0); ls0 += s[nb][0];
            s[nb][1] = fexp(s[nb][1] - nm0); ls0 += s[nb][1];
            s[nb][2] = fexp(s[nb][2] - nm1); ls1 += s[nb][2];
            s[nb][3] = fexp(s[nb][3] - nm1); ls1 += s[nb][3];
        }
        ls0 += __shfl_xor_sync(0xffffffffu, ls0, 1);
        ls0 += __shfl_xor_sync(0xffffffffu, ls0, 2);
        ls1 += __shfl_xor_sync(0xffffffffu, ls1, 1);
        ls1 += __shfl_xor_sync(0xffffffffu, ls1, 2);
        l0 = l0 * corr0 + ls0;
        l1 = l1 * corr1 + ls1;

#pragma unroll
        for (int nb = 0; nb < 8; nb++) {
            o[nb][0] *= corr0; o[nb][1] *= corr0;
            o[nb][2] *= corr1; o[nb][3] *= corr1;
        }

        // ---- O += P V (3-pass split, x4 trans B loads) ----
#pragma unroll
        for (int kc = 0; kc < 4; kc++) {
            unsigned ah[4], al[4];
            {
                float* p0 = s[2 * kc];
                float* p1 = s[2 * kc + 1];
                ah[0] = pack2bf(p0[0], p0[1]);
                ah[1] = pack2bf(p0[2], p0[3]);
                ah[2] = pack2bf(p1[0], p1[1]);
                ah[3] = pack2bf(p1[2], p1[3]);
                al[0] = pack2bf(p0[0] - bflo(ah[0]), p0[1] - bfhi(ah[0]));
                al[1] = pack2bf(p0[2] - bflo(ah[1]), p0[3] - bfhi(ah[1]));
                al[2] = pack2bf(p1[0] - bflo(ah[2]), p1[1] - bfhi(ah[2]));
                al[3] = pack2bf(p1[2] - bflo(ah[3]), p1[3] - bfhi(ah[3]));
            }
#pragma unroll
            for (int nbp = 0; nbp < 4; nbp++) {
                unsigned Bh[4], Bl[4];
                uint32_t off = (uint32_t)(((kc * 16 + (lane & 15)) * GP2 +
                                           (nbp * 2 + ((lane >> 4) & 1)) * 8) * 2);
                ldm_x4t(Bh, vh_u + off);
                ldm_x4t(Bl, vl_u + off);
                mma_bf16(o[2 * nbp],     ah, &Bh[0]);
                mma_bf16(o[2 * nbp + 1], ah, &Bh[2]);
                mma_bf16(o[2 * nbp],     ah, &Bl[0]);
                mma_bf16(o[2 * nbp + 1], ah, &Bl[2]);
                mma_bf16(o[2 * nbp],     al, &Bh[0]);
                mma_bf16(o[2 * nbp + 1], al, &Bh[2]);
            }
        }
    }

    // ---- epilogue ----
    const float i0 = 1.f / l0, i1 = 1.f / l1;
    float* out0 = g_attn + (size_t)(b * TT + rg0) * CC + h * HD + cbase;
    float* out1 = g_attn + (size_t)(b * TT + rg1) * CC + h * HD + cbase;
#pragma unroll
    for (int nb = 0; nb < 8; nb++) {
        *(float2*)(out0 + nb * 8) = make_float2(o[nb][0] * i0, o[nb][1] * i0);
        *(float2*)(out1 + nb * 8) = make_float2(o[nb][2] * i1, o[nb][3] * i1);
    }
}

// ---------------------------------------------------------------------------
extern "C" void kernel_launch(void* const* d_in, const int* in_sizes, int n_in,
                              void* d_out, int out_size)
{
    const float* x     = (const float*)d_in[0];   // (4096,1024)
    const float* w_qkv = (const float*)d_in[1];   // (3072,1024)
    const float* w_out = (const float*)d_in[2];   // (1024,1024)
    float* out = (float*)d_out;                   // (4096,1024)

    float* qkv;  cudaGetSymbolAddress((void**)&qkv,  g_qkv);
    float* attn; cudaGetSymbolAddress((void**)&attn, g_attn);

    const int M = BB * TT;

    static int attr_set = 0;
    if (!attr_set) {
        cudaFuncSetAttribute(gemm_bf16x3,
                             cudaFuncAttributeMaxDynamicSharedMemorySize,
                             GEMM_SMEM_BYTES);
        cudaFuncSetAttribute(attn_mma,
                             cudaFuncAttributeMaxDynamicSharedMemorySize,
                             ATTN_SMEM_BYTES);
        attr_set = 1;
    }

    gemm_bf16x3<<<dim3(C3 / 128, M / 128), 256, GEMM_SMEM_BYTES>>>(x, w_qkv, qkv, M, C3, CC);

    const int rope_total = BB * TT * HH * (HD / 2);
    rope_kernel<<<(rope_total + 255) / 256, 256>>>();

    attn_mma<<<dim3(TT / 128, BB * HH), 256, ATTN_SMEM_BYTES>>>();

    gemm_bf16x3<<<dim3(CC / 128, M / 128), 256, GEMM_SMEM_BYTES>>>(attn, w_out, out, M, CC, CC);
}

// round 11
// speedup vs baseline: 1.0136x; 1.0136x over previous
#include <cuda_runtime.h>
#include <cuda_bf16.h>
#include <math.h>
#include <stdint.h>

#define BB 2
#define TT 2048
#define CC 1024
#define HH 16
#define HD 64
#define C3 3072

__device__ float g_qkv[(size_t)BB * TT * C3];   // 4096 x 3072
__device__ float g_attn[(size_t)BB * TT * CC];  // 4096 x 1024

// ---------------------------------------------------------------------------
// mma / ldmatrix helpers
// ---------------------------------------------------------------------------
__device__ __forceinline__ void mma_bf16(float* c, const unsigned* a, const unsigned* b) {
    asm("mma.sync.aligned.m16n8k16.row.col.f32.bf16.bf16.f32 "
        "{%0,%1,%2,%3},{%4,%5,%6,%7},{%8,%9},{%0,%1,%2,%3};"
        : "+f"(c[0]), "+f"(c[1]), "+f"(c[2]), "+f"(c[3])
        : "r"(a[0]), "r"(a[1]), "r"(a[2]), "r"(a[3]), "r"(b[0]), "r"(b[1]));
}
__device__ __forceinline__ void ldm_x4(unsigned* r, uint32_t addr) {
    asm volatile("ldmatrix.sync.aligned.m8n8.x4.shared.b16 {%0,%1,%2,%3}, [%4];"
                 : "=r"(r[0]), "=r"(r[1]), "=r"(r[2]), "=r"(r[3]) : "r"(addr));
}
__device__ __forceinline__ void ldm_x4t(unsigned* r, uint32_t addr) {
    asm volatile("ldmatrix.sync.aligned.m8n8.x4.trans.shared.b16 {%0,%1,%2,%3}, [%4];"
                 : "=r"(r[0]), "=r"(r[1]), "=r"(r[2]), "=r"(r[3]) : "r"(addr));
}

__device__ __forceinline__ unsigned pack2bf(float lo, float hi) {
    unsigned r;
    asm("cvt.rn.bf16x2.f32 %0, %1, %2;" : "=r"(r) : "f"(hi), "f"(lo));
    return r;
}
__device__ __forceinline__ float bflo(unsigned u) { return __uint_as_float(u << 16); }
__device__ __forceinline__ float bfhi(unsigned u) { return __uint_as_float(u & 0xffff0000u); }

// fast exp on fma/alu pipes (no MUFU)
__device__ __forceinline__ float fexp(float x) {
    float y = x * 1.4426950408889634f;
    y = fmaxf(y, -126.0f);
    int ni = __float2int_rd(y);
    float f = y - (float)ni;
    float p = 0.0018775767f;
    p = fmaf(p, f, 0.0089893397f);
    p = fmaf(p, f, 0.0558282185f);
    p = fmaf(p, f, 0.2400789568f);
    p = fmaf(p, f, 0.6931531203f);
    p = fmaf(p, f, 0.9999999702f);
    return __uint_as_float(__float_as_uint(p) + ((unsigned)ni << 23));
}

__device__ __forceinline__ void split4(float4 v, uint2& hp, uint2& lp) {
    unsigned h01 = pack2bf(v.x, v.y);
    unsigned h23 = pack2bf(v.z, v.w);
    float r0 = v.x - bflo(h01);
    float r1 = v.y - bfhi(h01);
    float r2 = v.z - bflo(h23);
    float r3 = v.w - bfhi(h23);
    hp = make_uint2(h01, h23);
    lp = make_uint2(pack2bf(r0, r1), pack2bf(r2, r3));
}

// ---------------------------------------------------------------------------
// Tensor-core GEMM (NT), bf16 3-term split.
// CTA 128x128, BK=16, 256 threads (8 warps, 2x4), warp tile 64x32.
// 2 CTAs/SM so one CTA's mma covers the other's convert/sync bubbles.
// ---------------------------------------------------------------------------
#define GP 24
#define A_H (128 * GP)                  // 3072 halves
#define B_H (128 * GP)                  // 3072 halves
#define STAGE_H (2 * A_H + 2 * B_H)     // 12288 halves
#define GEMM_SMEM_BYTES (2 * STAGE_H * 2)   // 49152 B

__device__ __forceinline__ void cvt_store(unsigned short* hi_t, unsigned short* lo_t,
                                          int row, int col, float4 v) {
    uint2 hp, lp;
    split4(v, hp, lp);
    *(uint2*)&hi_t[row * GP + col] = hp;
    *(uint2*)&lo_t[row * GP + col] = lp;
}

__global__ __launch_bounds__(256, 2) void gemm_bf16x3(
    const float* __restrict__ A, const float* __restrict__ W,
    float* __restrict__ Cout, int M, int N, int K)
{
    extern __shared__ unsigned short sh[];

    const int tid = threadIdx.x;
    const int wid = tid >> 5;
    const int lane = tid & 31;
    const int warp_m = wid >> 2;        // 0..1 -> 64-row slices of 128
    const int warp_n = wid & 3;         // 0..3 -> 32-col slices of 128

    const float* Ap = A + (size_t)blockIdx.y * 128 * K;
    const float* Wp = W + (size_t)blockIdx.x * 128 * K;

    // 512 float4 slots per tile (128 rows x 4 chunks); thread covers rows r0, r0+64
    const int r0 = tid >> 2;
    const int c0 = (tid & 3) * 4;

    const uint32_t smem_u32 = (uint32_t)__cvta_generic_to_shared(sh);

    const int a_lrow = (lane & 7) + ((lane >> 3) & 1) * 8;
    const int a_lcol = ((lane >> 4) & 1) * 8;

    float acc[4][4][4];
#pragma unroll
    for (int i = 0; i < 4; i++)
#pragma unroll
        for (int j = 0; j < 4; j++)
#pragma unroll
            for (int q = 0; q < 4; q++) acc[i][j][q] = 0.f;

    const int nstage = K / 16;

    float4 va0 = *(const float4*)(Ap + (size_t)r0 * K + c0);
    float4 va1 = *(const float4*)(Ap + (size_t)(r0 + 64) * K + c0);
    float4 vb0 = *(const float4*)(Wp + (size_t)r0 * K + c0);
    float4 vb1 = *(const float4*)(Wp + (size_t)(r0 + 64) * K + c0);
    cvt_store(sh,           sh + A_H,           r0,      c0, va0);
    cvt_store(sh,           sh + A_H,           r0 + 64, c0, va1);
    cvt_store(sh + 2 * A_H, sh + 2 * A_H + B_H, r0,      c0, vb0);
    cvt_store(sh + 2 * A_H, sh + 2 * A_H + B_H, r0 + 64, c0, vb1);
    __syncthreads();

    for (int s = 0; s < nstage; s++) {
        if (s + 1 < nstage) {
            const int k0 = (s + 1) * 16;
            va0 = *(const float4*)(Ap + (size_t)r0 * K + k0 + c0);
            va1 = *(const float4*)(Ap + (size_t)(r0 + 64) * K + k0 + c0);
            vb0 = *(const float4*)(Wp + (size_t)r0 * K + k0 + c0);
            vb1 = *(const float4*)(Wp + (size_t)(r0 + 64) * K + k0 + c0);
        }
        {
            const uint32_t base = smem_u32 + (unsigned)(s & 1) * (STAGE_H * 2);
            const uint32_t baseAhi = base;
            const uint32_t baseAlo = base + A_H * 2;
            const uint32_t baseBhi = base + 2 * A_H * 2;
            const uint32_t baseBlo = base + (2 * A_H + B_H) * 2;

            // hold all B fragments (x4: two n-blocks per load)
            unsigned Bh[2][4], Bl[2][4];
#pragma unroll
            for (int anp = 0; anp < 2; anp++) {
                const uint32_t off = (uint32_t)(((warp_n * 32 + anp * 16 +
                                                  ((lane >> 4) & 1) * 8 + (lane & 7)) * GP +
                                                 ((lane >> 3) & 1) * 8) * 2);
                ldm_x4(Bh[anp], baseBhi + off);
                ldm_x4(Bl[anp], baseBlo + off);
            }
#pragma unroll
            for (int am = 0; am < 4; am++) {
                unsigned Ah[4], Al[4];
                const uint32_t off =
                    (uint32_t)(((warp_m * 64 + am * 16 + a_lrow) * GP + a_lcol) * 2);
                ldm_x4(Ah, baseAhi + off);
                ldm_x4(Al, baseAlo + off);
#pragma unroll
                for (int anp = 0; anp < 2; anp++) {
                    mma_bf16(acc[am][2 * anp],     Ah, &Bh[anp][0]);
                    mma_bf16(acc[am][2 * anp + 1], Ah, &Bh[anp][2]);
                    mma_bf16(acc[am][2 * anp],     Ah, &Bl[anp][0]);
                    mma_bf16(acc[am][2 * anp + 1], Ah, &Bl[anp][2]);
                    mma_bf16(acc[am][2 * anp],     Al, &Bh[anp][0]);
                    mma_bf16(acc[am][2 * anp + 1], Al, &Bh[anp][2]);
                }
            }
        }
        if (s + 1 < nstage) {
            unsigned short* st = sh + (unsigned)((s + 1) & 1) * STAGE_H;
            cvt_store(st,           st + A_H,           r0,      c0, va0);
            cvt_store(st,           st + A_H,           r0 + 64, c0, va1);
            cvt_store(st + 2 * A_H, st + 2 * A_H + B_H, r0,      c0, vb0);
            cvt_store(st + 2 * A_H, st + 2 * A_H + B_H, r0 + 64, c0, vb1);
            __syncthreads();
        }
    }

    const int mbase = blockIdx.y * 128 + warp_m * 64 + (lane >> 2);
    const int nbase = blockIdx.x * 128 + warp_n * 32 + (lane & 3) * 2;
#pragma unroll
    for (int am = 0; am < 4; am++) {
#pragma unroll
        for (int an = 0; an < 4; an++) {
            const int r = mbase + am * 16;
            const int c = nbase + an * 8;
            *(float2*)&Cout[(size_t)r * N + c]       = make_float2(acc[am][an][0], acc[am][an][1]);
            *(float2*)&Cout[(size_t)(r + 8) * N + c] = make_float2(acc[am][an][2], acc[am][an][3]);
        }
    }
}

// ---------------------------------------------------------------------------
// RoPE: in-place on q and k slices of g_qkv.
// ---------------------------------------------------------------------------
__global__ void rope_kernel()
{
    int i = blockIdx.x * blockDim.x + threadIdx.x;
    const int total = BB * TT * HH * (HD / 2);
    if (i >= total) return;

    int n = i >> 9;
    int r = i & 511;
    int h = r >> 5;
    int j = r & 31;
    int t = n & (TT - 1);

    float inv_freq = (float)exp(-(double)j * 0.28782313662425575);
    float f = (float)t * inv_freq;
    float c = cosf(f);
    float s = sinf(f);

    float* p = g_qkv + (size_t)n * C3 + h * HD + 2 * j;
    float qr = p[0], qi = p[1];
    p[0] = qr * c - qi * s;
    p[1] = qr * s + qi * c;

    float* pk = p + CC;
    float kr = pk[0], ki = pk[1];
    pk[0] = kr * c - ki * s;
    pk[1] = kr * s + ki * c;
}

// ---------------------------------------------------------------------------
// Tensor-core causal flash attention.
// CTA: 128 q-rows, 8 warps (16 rows/warp), 64-key tiles, dynamic smem.
// Q fragments re-loaded from smem each tile (frees 32 regs -> real 2 CTAs/SM).
// ---------------------------------------------------------------------------
#define GP2 72
#define KHI_O 0
#define KLO_O 4608
#define VHI_O 9216
#define VLO_O 13824
#define QHI_O 18432
#define QLO_O 27648
#define ATTN_SMEM_HALVES 36864
#define ATTN_SMEM_BYTES (ATTN_SMEM_HALVES * 2)   // 73728 B

__global__ __launch_bounds__(256, 2) void attn_mma()
{
    extern __shared__ unsigned short ash[];

    const int bh = blockIdx.y;
    const int b = bh >> 4;
    const int h = bh & 15;
    const int qtile = 15 - blockIdx.x;     // heavy tiles first
    const int q0 = qtile * 128;
    const int tid = threadIdx.x;
    const int wid = tid >> 5;
    const int lane = tid & 31;
    const float scale = 0.125f;

    const float* base = g_qkv + (size_t)b * TT * C3;

    const uint32_t sm_u = (uint32_t)__cvta_generic_to_shared(ash);
    const uint32_t kh_u = sm_u + KHI_O * 2;
    const uint32_t kl_u = sm_u + KLO_O * 2;
    const uint32_t vh_u = sm_u + VHI_O * 2;
    const uint32_t vl_u = sm_u + VLO_O * 2;
    const uint32_t qh_u = sm_u + QHI_O * 2;
    const uint32_t ql_u = sm_u + QLO_O * 2;

    const int a_lrow = (lane & 7) + ((lane >> 3) & 1) * 8;
    const int a_lcol = ((lane >> 4) & 1) * 8;

    // ---- stage Q (128 x 64) ----
#pragma unroll
    for (int it = 0; it < 8; it++) {
        int idx = tid + it * 256;               // 2048 float4 slots
        int r = idx >> 4, c4 = (idx & 15) * 4;
        float4 v = *(const float4*)(base + (size_t)(q0 + r) * C3 + h * HD + c4);
        uint2 hp, lp;
        split4(v, hp, lp);
        *(uint2*)&ash[QHI_O + r * GP2 + c4] = hp;
        *(uint2*)&ash[QLO_O + r * GP2 + c4] = lp;
    }
    __syncthreads();

    // per-kk Q fragment smem offsets (fragments re-loaded each tile)
    uint32_t qoff[4];
#pragma unroll
    for (int kk = 0; kk < 4; kk++)
        qoff[kk] = (uint32_t)(((wid * 16 + a_lrow) * GP2 + kk * 16 + a_lcol) * 2);

    float o[8][4];
#pragma unroll
    for (int nb = 0; nb < 8; nb++)
#pragma unroll
        for (int e = 0; e < 4; e++) o[nb][e] = 0.f;
    float m0 = -1e30f, m1 = -1e30f, l0 = 0.f, l1 = 0.f;

    const int rg0 = q0 + wid * 16 + (lane >> 2);
    const int rg1 = rg0 + 8;
    const int cbase = (lane & 3) * 2;

    const int nkt = 2 * qtile + 2;
    for (int kt = 0; kt < nkt; kt++) {
        const int k0 = kt * 64;
        __syncthreads();

        // ---- load K,V tile (64 x 64), split bf16 hi/lo ----
#pragma unroll
        for (int it = 0; it < 4; it++) {
            int idx = tid + it * 256;            // 1024 slots
            int r = idx >> 4, c4 = (idx & 15) * 4;
            const float* src = base + (size_t)(k0 + r) * C3 + CC + h * HD + c4;
            float4 kv = *(const float4*)src;
            float4 vv = *(const float4*)(src + CC);
            uint2 hp, lp;
            split4(kv, hp, lp);
            *(uint2*)&ash[KHI_O + r * GP2 + c4] = hp;
            *(uint2*)&ash[KLO_O + r * GP2 + c4] = lp;
            split4(vv, hp, lp);
            *(uint2*)&ash[VHI_O + r * GP2 + c4] = hp;
            *(uint2*)&ash[VLO_O + r * GP2 + c4] = lp;
        }
        __syncthreads();

        // ---- S = Q K^T (3-pass split, x4 B loads, Q frags from smem) ----
        float s[8][4];
#pragma unroll
        for (int nb = 0; nb < 8; nb++)
#pragma unroll
            for (int e = 0; e < 4; e++) s[nb][e] = 0.f;

#pragma unroll
        for (int kk = 0; kk < 4; kk++) {
            unsigned Qh[4], Ql[4];
            ldm_x4(Qh, qh_u + qoff[kk]);
            ldm_x4(Ql, ql_u + qoff[kk]);
#pragma unroll
            for (int nbp = 0; nbp < 4; nbp++) {
                unsigned Bh[4], Bl[4];
                uint32_t off = (uint32_t)(((nbp * 16 + ((lane >> 4) & 1) * 8 + (lane & 7)) * GP2 +
                                           kk * 16 + ((lane >> 3) & 1) * 8) * 2);
                ldm_x4(Bh, kh_u + off);
                ldm_x4(Bl, kl_u + off);
                mma_bf16(s[2 * nbp],     Qh, &Bh[0]);
                mma_bf16(s[2 * nbp + 1], Qh, &Bh[2]);
                mma_bf16(s[2 * nbp],     Qh, &Bl[0]);
                mma_bf16(s[2 * nbp + 1], Qh, &Bl[2]);
                mma_bf16(s[2 * nbp],     Ql, &Bh[0]);
                mma_bf16(s[2 * nbp + 1], Ql, &Bh[2]);
            }
        }

        // ---- scale + causal mask ----
        const bool diag = (kt >= 2 * qtile);
#pragma unroll
        for (int nb = 0; nb < 8; nb++) {
            int c0g = k0 + nb * 8 + cbase;
#pragma unroll
            for (int e = 0; e < 4; e++) {
                int col = c0g + (e & 1);
                int row = (e < 2) ? rg0 : rg1;
                float v = s[nb][e] * scale;
                if (diag && col > row) v = -1e30f;
                s[nb][e] = v;
            }
        }

        // ---- online softmax ----
        float mx0 = -1e30f, mx1 = -1e30f;
#pragma unroll
        for (int nb = 0; nb < 8; nb++) {
            mx0 = fmaxf(mx0, fmaxf(s[nb][0], s[nb][1]));
            mx1 = fmaxf(mx1, fmaxf(s[nb][2], s[nb][3]));
        }
        mx0 = fmaxf(mx0, __shfl_xor_sync(0xffffffffu, mx0, 1));
        mx0 = fmaxf(mx0, __shfl_xor_sync(0xffffffffu, mx0, 2));
        mx1 = fmaxf(mx1, __shfl_xor_sync(0xffffffffu, mx1, 1));
        mx1 = fmaxf(mx1, __shfl_xor_sync(0xffffffffu, mx1, 2));

        float nm0 = fmaxf(m0, mx0), nm1 = fmaxf(m1, mx1);
        float corr0 = fexp(m0 - nm0), corr1 = fexp(m1 - nm1);
        m0 = nm0; m1 = nm1;

        float ls0 = 0.f, ls1 = 0.f;
#pragma unroll
        for (int nb = 0; nb < 8; nb++) {
            s[nb][0] = fexp(s[nb][0] - nm0); ls0 += s[nb][0];
            s[nb][1] = fexp(s[nb][1] - nm0); ls0 += s[nb][1];
            s[nb][2] = fexp(s[nb][2] - nm1); ls1 += s[nb][2];
            s[nb][3] = fexp(s[nb][3] - nm1); ls1 += s[nb][3];
        }
        ls0 += __shfl_xor_sync(0xffffffffu, ls0, 1);
        ls0 += __shfl_xor_sync(0xffffffffu, ls0, 2);
        ls1 += __shfl_xor_sync(0xffffffffu, ls1, 1);
        ls1 += __shfl_xor_sync(0xffffffffu, ls1, 2);
        l0 = l0 * corr0 + ls0;
        l1 = l1 * corr1 + ls1;

#pragma unroll
        for (int nb = 0; nb < 8; nb++) {
            o[nb][0] *= corr0; o[nb][1] *= corr0;
            o[nb][2] *= corr1; o[nb][3] *= corr1;
        }

        // ---- O += P V (3-pass split, x4 trans B loads) ----
#pragma unroll
        for (int kc = 0; kc < 4; kc++) {
            unsigned ah[4], al[4];
            {
                float* p0 = s[2 * kc];
                float* p1 = s[2 * kc + 1];
                ah[0] = pack2bf(p0[0], p0[1]);
                ah[1] = pack2bf(p0[2], p0[3]);
                ah[2] = pack2bf(p1[0], p1[1]);
                ah[3] = pack2bf(p1[2], p1[3]);
                al[0] = pack2bf(p0[0] - bflo(ah[0]), p0[1] - bfhi(ah[0]));
                al[1] = pack2bf(p0[2] - bflo(ah[1]), p0[3] - bfhi(ah[1]));
                al[2] = pack2bf(p1[0] - bflo(ah[2]), p1[1] - bfhi(ah[2]));
                al[3] = pack2bf(p1[2] - bflo(ah[3]), p1[3] - bfhi(ah[3]));
            }
#pragma unroll
            for (int nbp = 0; nbp < 4; nbp++) {
                unsigned Bh[4], Bl[4];
                uint32_t off = (uint32_t)(((kc * 16 + (lane & 15)) * GP2 +
                                           (nbp * 2 + ((lane >> 4) & 1)) * 8) * 2);
                ldm_x4t(Bh, vh_u + off);
                ldm_x4t(Bl, vl_u + off);
                mma_bf16(o[2 * nbp],     ah, &Bh[0]);
                mma_bf16(o[2 * nbp + 1], ah, &Bh[2]);
                mma_bf16(o[2 * nbp],     ah, &Bl[0]);
                mma_bf16(o[2 * nbp + 1], ah, &Bl[2]);
                mma_bf16(o[2 * nbp],     al, &Bh[0]);
                mma_bf16(o[2 * nbp + 1], al, &Bh[2]);
            }
        }
    }

    // ---- epilogue ----
    const float i0 = 1.f / l0, i1 = 1.f / l1;
    float* out0 = g_attn + (size_t)(b * TT + rg0) * CC + h * HD + cbase;
    float* out1 = g_attn + (size_t)(b * TT + rg1) * CC + h * HD + cbase;
#pragma unroll
    for (int nb = 0; nb < 8; nb++) {
        *(float2*)(out0 + nb * 8) = make_float2(o[nb][0] * i0, o[nb][1] * i0);
        *(float2*)(out1 + nb * 8) = make_float2(o[nb][2] * i1, o[nb][3] * i1);
    }
}

// ---------------------------------------------------------------------------
extern "C" void kernel_launch(void* const* d_in, const int* in_sizes, int n_in,
                              void* d_out, int out_size)
{
    const float* x     = (const float*)d_in[0];   // (4096,1024)
    const float* w_qkv = (const float*)d_in[1];   // (3072,1024)
    const float* w_out = (const float*)d_in[2];   // (1024,1024)
    float* out = (float*)d_out;                   // (4096,1024)

    float* qkv;  cudaGetSymbolAddress((void**)&qkv,  g_qkv);
    float* attn; cudaGetSymbolAddress((void**)&attn, g_attn);

    const int M = BB * TT;

    static int attr_set = 0;
    if (!attr_set) {
        cudaFuncSetAttribute(gemm_bf16x3,
                             cudaFuncAttributeMaxDynamicSharedMemorySize,
                             GEMM_SMEM_BYTES);
        cudaFuncSetAttribute(attn_mma,
                             cudaFuncAttributeMaxDynamicSharedMemorySize,
                             ATTN_SMEM_BYTES);
        attr_set = 1;
    }

    gemm_bf16x3<<<dim3(C3 / 128, M / 128), 256, GEMM_SMEM_BYTES>>>(x, w_qkv, qkv, M, C3, CC);

    const int rope_total = BB * TT * HH * (HD / 2);
    rope_kernel<<<(rope_total + 255) / 256, 256>>>();

    attn_mma<<<dim3(TT / 128, BB * HH), 256, ATTN_SMEM_BYTES>>>();

    gemm_bf16x3<<<dim3(CC / 128, M / 128), 256, GEMM_SMEM_BYTES>>>(attn, w_out, out, M, CC, CC);
}

// round 13
// speedup vs baseline: 1.1409x; 1.1256x over previous
#include <cuda_runtime.h>
#include <cuda_bf16.h>
#include <math.h>
#include <stdint.h>

#define BB 2
#define TT 2048
#define CC 1024
#define HH 16
#define HD 64
#define C3 3072

__device__ float g_qkv[(size_t)BB * TT * C3];   // 4096 x 3072
__device__ float g_attn[(size_t)BB * TT * CC];  // 4096 x 1024

// ---------------------------------------------------------------------------
// mma / ldmatrix helpers
// ---------------------------------------------------------------------------
__device__ __forceinline__ void mma_bf16(float* c, const unsigned* a, const unsigned* b) {
    asm("mma.sync.aligned.m16n8k16.row.col.f32.bf16.bf16.f32 "
        "{%0,%1,%2,%3},{%4,%5,%6,%7},{%8,%9},{%0,%1,%2,%3};"
        : "+f"(c[0]), "+f"(c[1]), "+f"(c[2]), "+f"(c[3])
        : "r"(a[0]), "r"(a[1]), "r"(a[2]), "r"(a[3]), "r"(b[0]), "r"(b[1]));
}
__device__ __forceinline__ void ldm_x4(unsigned* r, uint32_t addr) {
    asm volatile("ldmatrix.sync.aligned.m8n8.x4.shared.b16 {%0,%1,%2,%3}, [%4];"
                 : "=r"(r[0]), "=r"(r[1]), "=r"(r[2]), "=r"(r[3]) : "r"(addr));
}
__device__ __forceinline__ void ldm_x4t(unsigned* r, uint32_t addr) {
    asm volatile("ldmatrix.sync.aligned.m8n8.x4.trans.shared.b16 {%0,%1,%2,%3}, [%4];"
                 : "=r"(r[0]), "=r"(r[1]), "=r"(r[2]), "=r"(r[3]) : "r"(addr));
}

__device__ __forceinline__ unsigned pack2bf(float lo, float hi) {
    unsigned r;
    asm("cvt.rn.bf16x2.f32 %0, %1, %2;" : "=r"(r) : "f"(hi), "f"(lo));
    return r;
}
__device__ __forceinline__ float bflo(unsigned u) { return __uint_as_float(u << 16); }
__device__ __forceinline__ float bfhi(unsigned u) { return __uint_as_float(u & 0xffff0000u); }

// fast exp on fma/alu pipes (no MUFU)
__device__ __forceinline__ float fexp(float x) {
    float y = x * 1.4426950408889634f;
    y = fmaxf(y, -126.0f);
    int ni = __float2int_rd(y);
    float f = y - (float)ni;
    float p = 0.0018775767f;
    p = fmaf(p, f, 0.0089893397f);
    p = fmaf(p, f, 0.0558282185f);
    p = fmaf(p, f, 0.2400789568f);
    p = fmaf(p, f, 0.6931531203f);
    p = fmaf(p, f, 0.9999999702f);
    return __uint_as_float(__float_as_uint(p) + ((unsigned)ni << 23));
}

__device__ __forceinline__ void split4(float4 v, uint2& hp, uint2& lp) {
    unsigned h01 = pack2bf(v.x, v.y);
    unsigned h23 = pack2bf(v.z, v.w);
    float r0 = v.x - bflo(h01);
    float r1 = v.y - bfhi(h01);
    float r2 = v.z - bflo(h23);
    float r3 = v.w - bfhi(h23);
    hp = make_uint2(h01, h23);
    lp = make_uint2(pack2bf(r0, r1), pack2bf(r2, r3));
}

// ---------------------------------------------------------------------------
// Tensor-core GEMM (NT), bf16 3-term split, optional fused RoPE epilogue.
// CTA 128x128, BK=16, 256 threads (8 warps, 2x4), warp tile 64x32, 2 CTAs/SM.
// ---------------------------------------------------------------------------
#define GP 24
#define A_H (128 * GP)                  // 3072 halves
#define B_H (128 * GP)                  // 3072 halves
#define STAGE_H (2 * A_H + 2 * B_H)     // 12288 halves
#define GEMM_SMEM_BYTES (2 * STAGE_H * 2)   // 49152 B

__device__ __forceinline__ void cvt_store(unsigned short* hi_t, unsigned short* lo_t,
                                          int row, int col, float4 v) {
    uint2 hp, lp;
    split4(v, hp, lp);
    *(uint2*)&hi_t[row * GP + col] = hp;
    *(uint2*)&lo_t[row * GP + col] = lp;
}

__global__ __launch_bounds__(256, 2) void gemm_bf16x3(
    const float* __restrict__ A, const float* __restrict__ W,
    float* __restrict__ Cout, int M, int N, int K, int do_rope)
{
    extern __shared__ unsigned short sh[];

    const int tid = threadIdx.x;
    const int wid = tid >> 5;
    const int lane = tid & 31;
    const int warp_m = wid >> 2;        // 0..1 -> 64-row slices of 128
    const int warp_n = wid & 3;         // 0..3 -> 32-col slices of 128

    const float* Ap = A + (size_t)blockIdx.y * 128 * K;
    const float* Wp = W + (size_t)blockIdx.x * 128 * K;

    const int r0 = tid >> 2;
    const int c0 = (tid & 3) * 4;

    const uint32_t smem_u32 = (uint32_t)__cvta_generic_to_shared(sh);

    const int a_lrow = (lane & 7) + ((lane >> 3) & 1) * 8;
    const int a_lcol = ((lane >> 4) & 1) * 8;

    float acc[4][4][4];
#pragma unroll
    for (int i = 0; i < 4; i++)
#pragma unroll
        for (int j = 0; j < 4; j++)
#pragma unroll
            for (int q = 0; q < 4; q++) acc[i][j][q] = 0.f;

    const int nstage = K / 16;

    float4 va0 = *(const float4*)(Ap + (size_t)r0 * K + c0);
    float4 va1 = *(const float4*)(Ap + (size_t)(r0 + 64) * K + c0);
    float4 vb0 = *(const float4*)(Wp + (size_t)r0 * K + c0);
    float4 vb1 = *(const float4*)(Wp + (size_t)(r0 + 64) * K + c0);
    cvt_store(sh,           sh + A_H,           r0,      c0, va0);
    cvt_store(sh,           sh + A_H,           r0 + 64, c0, va1);
    cvt_store(sh + 2 * A_H, sh + 2 * A_H + B_H, r0,      c0, vb0);
    cvt_store(sh + 2 * A_H, sh + 2 * A_H + B_H, r0 + 64, c0, vb1);
    __syncthreads();

    for (int s = 0; s < nstage; s++) {
        if (s + 1 < nstage) {
            const int k0 = (s + 1) * 16;
            va0 = *(const float4*)(Ap + (size_t)r0 * K + k0 + c0);
            va1 = *(const float4*)(Ap + (size_t)(r0 + 64) * K + k0 + c0);
            vb0 = *(const float4*)(Wp + (size_t)r0 * K + k0 + c0);
            vb1 = *(const float4*)(Wp + (size_t)(r0 + 64) * K + k0 + c0);
        }
        {
            const uint32_t base = smem_u32 + (unsigned)(s & 1) * (STAGE_H * 2);
            const uint32_t baseAhi = base;
            const uint32_t baseAlo = base + A_H * 2;
            const uint32_t baseBhi = base + 2 * A_H * 2;
            const uint32_t baseBlo = base + (2 * A_H + B_H) * 2;

            unsigned Bh[2][4], Bl[2][4];
#pragma unroll
            for (int anp = 0; anp < 2; anp++) {
                const uint32_t off = (uint32_t)(((warp_n * 32 + anp * 16 +
                                                  ((lane >> 4) & 1) * 8 + (lane & 7)) * GP +
                                                 ((lane >> 3) & 1) * 8) * 2);
                ldm_x4(Bh[anp], baseBhi + off);
                ldm_x4(Bl[anp], baseBlo + off);
            }
#pragma unroll
            for (int am = 0; am < 4; am++) {
                unsigned Ah[4], Al[4];
                const uint32_t off =
                    (uint32_t)(((warp_m * 64 + am * 16 + a_lrow) * GP + a_lcol) * 2);
                ldm_x4(Ah, baseAhi + off);
                ldm_x4(Al, baseAlo + off);
#pragma unroll
                for (int anp = 0; anp < 2; anp++) {
                    mma_bf16(acc[am][2 * anp],     Ah, &Bh[anp][0]);
                    mma_bf16(acc[am][2 * anp + 1], Ah, &Bh[anp][2]);
                    mma_bf16(acc[am][2 * anp],     Ah, &Bl[anp][0]);
                    mma_bf16(acc[am][2 * anp + 1], Ah, &Bl[anp][2]);
                    mma_bf16(acc[am][2 * anp],     Al, &Bh[anp][0]);
                    mma_bf16(acc[am][2 * anp + 1], Al, &Bh[anp][2]);
                }
            }
        }
        if (s + 1 < nstage) {
            unsigned short* st = sh + (unsigned)((s + 1) & 1) * STAGE_H;
            cvt_store(st,           st + A_H,           r0,      c0, va0);
            cvt_store(st,           st + A_H,           r0 + 64, c0, va1);
            cvt_store(st + 2 * A_H, st + 2 * A_H + B_H, r0,      c0, vb0);
            cvt_store(st + 2 * A_H, st + 2 * A_H + B_H, r0 + 64, c0, vb1);
            __syncthreads();
        }
    }

    // Epilogue (optionally fused RoPE on Q/K columns: pairs are (e0,e1)/(e2,e3))
    const int mbase = blockIdx.y * 128 + warp_m * 64 + (lane >> 2);
    const int nbase = blockIdx.x * 128 + warp_n * 32 + (lane & 3) * 2;
#pragma unroll
    for (int am = 0; am < 4; am++) {
#pragma unroll
        for (int an = 0; an < 4; an++) {
            const int r = mbase + am * 16;
            const int c = nbase + an * 8;
            float e0 = acc[am][an][0], e1 = acc[am][an][1];
            float e2 = acc[am][an][2], e3 = acc[am][an][3];
            if (do_rope && c < 2048) {
                // pair index within head; inv_freq = 10000^(-j/32)
                int j = (c & 63) >> 1;
                float invf = exp2f(-(float)j * 0.41524101186092029f);
                float f0 = (float)(r & (TT - 1)) * invf;
                float f1 = (float)((r + 8) & (TT - 1)) * invf;
                float s0, c0f, s1, c1f;
                sincosf(f0, &s0, &c0f);
                sincosf(f1, &s1, &c1f);
                float t0 = e0 * c0f - e1 * s0;
                float t1 = e0 * s0 + e1 * c0f;
                float t2 = e2 * c1f - e3 * s1;
                float t3 = e2 * s1 + e3 * c1f;
                e0 = t0; e1 = t1; e2 = t2; e3 = t3;
            }
            *(float2*)&Cout[(size_t)r * N + c]       = make_float2(e0, e1);
            *(float2*)&Cout[(size_t)(r + 8) * N + c] = make_float2(e2, e3);
        }
    }
}

// ---------------------------------------------------------------------------
// Tensor-core causal flash attention.
// CTA: 128 q-rows, 8 warps (16 rows/warp), 64-key tiles, dynamic smem.
// Scale folded into Q; PV full 3-pass split (P-lo pass is load-bearing).
// ---------------------------------------------------------------------------
#define GP2 72
#define KHI_O 0
#define KLO_O 4608
#define VHI_O 9216
#define VLO_O 13824
#define QHI_O 18432
#define QLO_O 27648
#define ATTN_SMEM_HALVES 36864
#define ATTN_SMEM_BYTES (ATTN_SMEM_HALVES * 2)   // 73728 B

__global__ __launch_bounds__(256, 2) void attn_mma()
{
    extern __shared__ unsigned short ash[];

    const int bh = blockIdx.y;
    const int b = bh >> 4;
    const int h = bh & 15;
    const int qtile = 15 - blockIdx.x;     // heavy tiles first
    const int q0 = qtile * 128;
    const int tid = threadIdx.x;
    const int wid = tid >> 5;
    const int lane = tid & 31;

    const float* base = g_qkv + (size_t)b * TT * C3;

    const uint32_t sm_u = (uint32_t)__cvta_generic_to_shared(ash);
    const uint32_t kh_u = sm_u + KHI_O * 2;
    const uint32_t kl_u = sm_u + KLO_O * 2;
    const uint32_t vh_u = sm_u + VHI_O * 2;
    const uint32_t vl_u = sm_u + VLO_O * 2;
    const uint32_t qh_u = sm_u + QHI_O * 2;
    const uint32_t ql_u = sm_u + QLO_O * 2;

    const int a_lrow = (lane & 7) + ((lane >> 3) & 1) * 8;
    const int a_lcol = ((lane >> 4) & 1) * 8;

    // ---- stage Q (128 x 64), scale 1/sqrt(64) folded in ----
#pragma unroll
    for (int it = 0; it < 8; it++) {
        int idx = tid + it * 256;               // 2048 float4 slots
        int r = idx >> 4, c4 = (idx & 15) * 4;
        float4 v = *(const float4*)(base + (size_t)(q0 + r) * C3 + h * HD + c4);
        v.x *= 0.125f; v.y *= 0.125f; v.z *= 0.125f; v.w *= 0.125f;
        uint2 hp, lp;
        split4(v, hp, lp);
        *(uint2*)&ash[QHI_O + r * GP2 + c4] = hp;
        *(uint2*)&ash[QLO_O + r * GP2 + c4] = lp;
    }
    __syncthreads();

    // per-kk Q fragment smem offsets (fragments re-loaded each tile)
    uint32_t qoff[4];
#pragma unroll
    for (int kk = 0; kk < 4; kk++)
        qoff[kk] = (uint32_t)(((wid * 16 + a_lrow) * GP2 + kk * 16 + a_lcol) * 2);

    float o[8][4];
#pragma unroll
    for (int nb = 0; nb < 8; nb++)
#pragma unroll
        for (int e = 0; e < 4; e++) o[nb][e] = 0.f;
    float m0 = -1e30f, m1 = -1e30f, l0 = 0.f, l1 = 0.f;

    const int rg0 = q0 + wid * 16 + (lane >> 2);
    const int rg1 = rg0 + 8;
    const int cbase = (lane & 3) * 2;

    const int nkt = 2 * qtile + 2;
    for (int kt = 0; kt < nkt; kt++) {
        const int k0 = kt * 64;
        __syncthreads();

        // ---- load K,V tile (64 x 64), split bf16 hi/lo ----
#pragma unroll
        for (int it = 0; it < 4; it++) {
            int idx = tid + it * 256;            // 1024 slots
            int r = idx >> 4, c4 = (idx & 15) * 4;
            const float* src = base + (size_t)(k0 + r) * C3 + CC + h * HD + c4;
            float4 kv = *(const float4*)src;
            float4 vv = *(const float4*)(src + CC);
            uint2 hp, lp;
            split4(kv, hp, lp);
            *(uint2*)&ash[KHI_O + r * GP2 + c4] = hp;
            *(uint2*)&ash[KLO_O + r * GP2 + c4] = lp;
            split4(vv, hp, lp);
            *(uint2*)&ash[VHI_O + r * GP2 + c4] = hp;
            *(uint2*)&ash[VLO_O + r * GP2 + c4] = lp;
        }
        __syncthreads();

        // ---- S = Q K^T (3-pass split, x4 B loads, Q frags from smem) ----
        float s[8][4];
#pragma unroll
        for (int nb = 0; nb < 8; nb++)
#pragma unroll
            for (int e = 0; e < 4; e++) s[nb][e] = 0.f;

#pragma unroll
        for (int kk = 0; kk < 4; kk++) {
            unsigned Qh[4], Ql[4];
            ldm_x4(Qh, qh_u + qoff[kk]);
            ldm_x4(Ql, ql_u + qoff[kk]);
#pragma unroll
            for (int nbp = 0; nbp < 4; nbp++) {
                unsigned Bh[4], Bl[4];
                uint32_t off = (uint32_t)(((nbp * 16 + ((lane >> 4) & 1) * 8 + (lane & 7)) * GP2 +
                                           kk * 16 + ((lane >> 3) & 1) * 8) * 2);
                ldm_x4(Bh, kh_u + off);
                ldm_x4(Bl, kl_u + off);
                mma_bf16(s[2 * nbp],     Qh, &Bh[0]);
                mma_bf16(s[2 * nbp + 1], Qh, &Bh[2]);
                mma_bf16(s[2 * nbp],     Qh, &Bl[0]);
                mma_bf16(s[2 * nbp + 1], Qh, &Bl[2]);
                mma_bf16(s[2 * nbp],     Ql, &Bh[0]);
                mma_bf16(s[2 * nbp + 1], Ql, &Bh[2]);
            }
        }

        // ---- causal mask (scale already folded into Q) ----
        const bool diag = (kt >= 2 * qtile);
        if (diag) {
#pragma unroll
            for (int nb = 0; nb < 8; nb++) {
                int c0g = k0 + nb * 8 + cbase;
#pragma unroll
                for (int e = 0; e < 4; e++) {
                    int col = c0g + (e & 1);
                    int row = (e < 2) ? rg0 : rg1;
                    if (col > row) s[nb][e] = -1e30f;
                }
            }
        }

        // ---- online softmax ----
        float mx0 = -1e30f, mx1 = -1e30f;
#pragma unroll
        for (int nb = 0; nb < 8; nb++) {
            mx0 = fmaxf(mx0, fmaxf(s[nb][0], s[nb][1]));
            mx1 = fmaxf(mx1, fmaxf(s[nb][2], s[nb][3]));
        }
        mx0 = fmaxf(mx0, __shfl_xor_sync(0xffffffffu, mx0, 1));
        mx0 = fmaxf(mx0, __shfl_xor_sync(0xffffffffu, mx0, 2));
        mx1 = fmaxf(mx1, __shfl_xor_sync(0xffffffffu, mx1, 1));
        mx1 = fmaxf(mx1, __shfl_xor_sync(0xffffffffu, mx1, 2));

        float nm0 = fmaxf(m0, mx0), nm1 = fmaxf(m1, mx1);
        float corr0 = fexp(m0 - nm0), corr1 = fexp(m1 - nm1);
        m0 = nm0; m1 = nm1;

        float ls0 = 0.f, ls1 = 0.f;
#pragma unroll
        for (int nb = 0; nb < 8; nb++) {
            s[nb][0] = fexp(s[nb][0] - nm0); ls0 += s[nb][0];
            s[nb][1] = fexp(s[nb][1] - nm0); ls0 += s[nb][1];
            s[nb][2] = fexp(s[nb][2] - nm1); ls1 += s[nb][2];
            s[nb][3] = fexp(s[nb][3] - nm1); ls1 += s[nb][3];
        }
        ls0 += __shfl_xor_sync(0xffffffffu, ls0, 1);
        ls0 += __shfl_xor_sync(0xffffffffu, ls0, 2);
        ls1 += __shfl_xor_sync(0xffffffffu, ls1, 1);
        ls1 += __shfl_xor_sync(0xffffffffu, ls1, 2);
        l0 = l0 * corr0 + ls0;
        l1 = l1 * corr1 + ls1;

#pragma unroll
        for (int nb = 0; nb < 8; nb++) {
            o[nb][0] *= corr0; o[nb][1] *= corr0;
            o[nb][2] *= corr1; o[nb][3] *= corr1;
        }

        // ---- O += P V (3-pass split, x4 trans B loads) ----
#pragma unroll
        for (int kc = 0; kc < 4; kc++) {
            unsigned ah[4], al[4];
            {
                float* p0 = s[2 * kc];
                float* p1 = s[2 * kc + 1];
                ah[0] = pack2bf(p0[0], p0[1]);
                ah[1] = pack2bf(p0[2], p0[3]);
                ah[2] = pack2bf(p1[0], p1[1]);
                ah[3] = pack2bf(p1[2], p1[3]);
                al[0] = pack2bf(p0[0] - bflo(ah[0]), p0[1] - bfhi(ah[0]));
                al[1] = pack2bf(p0[2] - bflo(ah[1]), p0[3] - bfhi(ah[1]));
                al[2] = pack2bf(p1[0] - bflo(ah[2]), p1[1] - bfhi(ah[2]));
                al[3] = pack2bf(p1[2] - bflo(ah[3]), p1[3] - bfhi(ah[3]));
            }
#pragma unroll
            for (int nbp = 0; nbp < 4; nbp++) {
                unsigned Bh[4], Bl[4];
                uint32_t off = (uint32_t)(((kc * 16 + (lane & 15)) * GP2 +
                                           (nbp * 2 + ((lane >> 4) & 1)) * 8) * 2);
                ldm_x4t(Bh, vh_u + off);
                ldm_x4t(Bl, vl_u + off);
                mma_bf16(o[2 * nbp],     ah, &Bh[0]);
                mma_bf16(o[2 * nbp + 1], ah, &Bh[2]);
                mma_bf16(o[2 * nbp],     ah, &Bl[0]);
                mma_bf16(o[2 * nbp + 1], ah, &Bl[2]);
                mma_bf16(o[2 * nbp],     al, &Bh[0]);
                mma_bf16(o[2 * nbp + 1], al, &Bh[2]);
            }
        }
    }

    // ---- epilogue ----
    const float i0 = 1.f / l0, i1 = 1.f / l1;
    float* out0 = g_attn + (size_t)(b * TT + rg0) * CC + h * HD + cbase;
    float* out1 = g_attn + (size_t)(b * TT + rg1) * CC + h * HD + cbase;
#pragma unroll
    for (int nb = 0; nb < 8; nb++) {
        *(float2*)(out0 + nb * 8) = make_float2(o[nb][0] * i0, o[nb][1] * i0);
        *(float2*)(out1 + nb * 8) = make_float2(o[nb][2] * i1, o[nb][3] * i1);
    }
}

// ---------------------------------------------------------------------------
extern "C" void kernel_launch(void* const* d_in, const int* in_sizes, int n_in,
                              void* d_out, int out_size)
{
    const float* x     = (const float*)d_in[0];   // (4096,1024)
    const float* w_qkv = (const float*)d_in[1];   // (3072,1024)
    const float* w_out = (const float*)d_in[2];   // (1024,1024)
    float* out = (float*)d_out;                   // (4096,1024)

    float* qkv;  cudaGetSymbolAddress((void**)&qkv,  g_qkv);
    float* attn; cudaGetSymbolAddress((void**)&attn, g_attn);

    const int M = BB * TT;

    static int attr_set = 0;
    if (!attr_set) {
        cudaFuncSetAttribute(gemm_bf16x3,
                             cudaFuncAttributeMaxDynamicSharedMemorySize,
                             GEMM_SMEM_BYTES);
        cudaFuncSetAttribute(attn_mma,
                             cudaFuncAttributeMaxDynamicSharedMemorySize,
                             ATTN_SMEM_BYTES);
        attr_set = 1;
    }

    // 1) qkv = x @ w_qkv^T with fused RoPE on Q/K columns
    gemm_bf16x3<<<dim3(C3 / 128, M / 128), 256, GEMM_SMEM_BYTES>>>(x, w_qkv, qkv, M, C3, CC, 1);

    // 2) attention
    attn_mma<<<dim3(TT / 128, BB * HH), 256, ATTN_SMEM_BYTES>>>();

    // 3) out = attn @ w_out^T
    gemm_bf16x3<<<dim3(CC / 128, M / 128), 256, GEMM_SMEM_BYTES>>>(attn, w_out, out, M, CC, CC, 0);
}

// round 14
// speedup vs baseline: 1.1439x; 1.0027x over previous
#include <cuda_runtime.h>
#include <cuda_bf16.h>
#include <math.h>
#include <stdint.h>

#define BB 2
#define TT 2048
#define CC 1024
#define HH 16
#define HD 64
#define C3 3072

__device__ float g_qkv[(size_t)BB * TT * C3];   // 4096 x 3072
__device__ float g_attn[(size_t)BB * TT * CC];  // 4096 x 1024

// ---------------------------------------------------------------------------
// mma / ldmatrix helpers
// ---------------------------------------------------------------------------
__device__ __forceinline__ void mma_bf16(float* c, const unsigned* a, const unsigned* b) {
    asm("mma.sync.aligned.m16n8k16.row.col.f32.bf16.bf16.f32 "
        "{%0,%1,%2,%3},{%4,%5,%6,%7},{%8,%9},{%0,%1,%2,%3};"
        : "+f"(c[0]), "+f"(c[1]), "+f"(c[2]), "+f"(c[3])
        : "r"(a[0]), "r"(a[1]), "r"(a[2]), "r"(a[3]), "r"(b[0]), "r"(b[1]));
}
__device__ __forceinline__ void ldm_x4(unsigned* r, uint32_t addr) {
    asm volatile("ldmatrix.sync.aligned.m8n8.x4.shared.b16 {%0,%1,%2,%3}, [%4];"
                 : "=r"(r[0]), "=r"(r[1]), "=r"(r[2]), "=r"(r[3]) : "r"(addr));
}
__device__ __forceinline__ void ldm_x4t(unsigned* r, uint32_t addr) {
    asm volatile("ldmatrix.sync.aligned.m8n8.x4.trans.shared.b16 {%0,%1,%2,%3}, [%4];"
                 : "=r"(r[0]), "=r"(r[1]), "=r"(r[2]), "=r"(r[3]) : "r"(addr));
}

__device__ __forceinline__ unsigned pack2bf(float lo, float hi) {
    unsigned r;
    asm("cvt.rn.bf16x2.f32 %0, %1, %2;" : "=r"(r) : "f"(hi), "f"(lo));
    return r;
}
__device__ __forceinline__ float bflo(unsigned u) { return __uint_as_float(u << 16); }
__device__ __forceinline__ float bfhi(unsigned u) { return __uint_as_float(u & 0xffff0000u); }

// fast exp on fma/alu pipes (no MUFU)
__device__ __forceinline__ float fexp(float x) {
    float y = x * 1.4426950408889634f;
    y = fmaxf(y, -126.0f);
    int ni = __float2int_rd(y);
    float f = y - (float)ni;
    float p = 0.0018775767f;
    p = fmaf(p, f, 0.0089893397f);
    p = fmaf(p, f, 0.0558282185f);
    p = fmaf(p, f, 0.2400789568f);
    p = fmaf(p, f, 0.6931531203f);
    p = fmaf(p, f, 0.9999999702f);
    return __uint_as_float(__float_as_uint(p) + ((unsigned)ni << 23));
}

__device__ __forceinline__ void split4(float4 v, uint2& hp, uint2& lp) {
    unsigned h01 = pack2bf(v.x, v.y);
    unsigned h23 = pack2bf(v.z, v.w);
    float r0 = v.x - bflo(h01);
    float r1 = v.y - bfhi(h01);
    float r2 = v.z - bflo(h23);
    float r3 = v.w - bfhi(h23);
    hp = make_uint2(h01, h23);
    lp = make_uint2(pack2bf(r0, r1), pack2bf(r2, r3));
}

// ---------------------------------------------------------------------------
// Tensor-core GEMM (NT), bf16 3-term split, optional fused RoPE epilogue.
// CTA 128x128, BK=16, 256 threads (8 warps, 2x4), warp tile 64x32, 2 CTAs/SM.
// ---------------------------------------------------------------------------
#define GP 24
#define A_H (128 * GP)                  // 3072 halves
#define B_H (128 * GP)                  // 3072 halves
#define STAGE_H (2 * A_H + 2 * B_H)     // 12288 halves
#define GEMM_SMEM_BYTES (2 * STAGE_H * 2)   // 49152 B

__device__ __forceinline__ void cvt_store(unsigned short* hi_t, unsigned short* lo_t,
                                          int row, int col, float4 v) {
    uint2 hp, lp;
    split4(v, hp, lp);
    *(uint2*)&hi_t[row * GP + col] = hp;
    *(uint2*)&lo_t[row * GP + col] = lp;
}

__global__ __launch_bounds__(256, 2) void gemm_bf16x3(
    const float* __restrict__ A, const float* __restrict__ W,
    float* __restrict__ Cout, int M, int N, int K, int do_rope)
{
    extern __shared__ unsigned short sh[];

    const int tid = threadIdx.x;
    const int wid = tid >> 5;
    const int lane = tid & 31;
    const int warp_m = wid >> 2;        // 0..1 -> 64-row slices of 128
    const int warp_n = wid & 3;         // 0..3 -> 32-col slices of 128

    const float* Ap = A + (size_t)blockIdx.y * 128 * K;
    const float* Wp = W + (size_t)blockIdx.x * 128 * K;

    const int r0 = tid >> 2;
    const int c0 = (tid & 3) * 4;

    const uint32_t smem_u32 = (uint32_t)__cvta_generic_to_shared(sh);

    const int a_lrow = (lane & 7) + ((lane >> 3) & 1) * 8;
    const int a_lcol = ((lane >> 4) & 1) * 8;

    float acc[4][4][4];
#pragma unroll
    for (int i = 0; i < 4; i++)
#pragma unroll
        for (int j = 0; j < 4; j++)
#pragma unroll
            for (int q = 0; q < 4; q++) acc[i][j][q] = 0.f;

    const int nstage = K / 16;

    float4 va0 = *(const float4*)(Ap + (size_t)r0 * K + c0);
    float4 va1 = *(const float4*)(Ap + (size_t)(r0 + 64) * K + c0);
    float4 vb0 = *(const float4*)(Wp + (size_t)r0 * K + c0);
    float4 vb1 = *(const float4*)(Wp + (size_t)(r0 + 64) * K + c0);
    cvt_store(sh,           sh + A_H,           r0,      c0, va0);
    cvt_store(sh,           sh + A_H,           r0 + 64, c0, va1);
    cvt_store(sh + 2 * A_H, sh + 2 * A_H + B_H, r0,      c0, vb0);
    cvt_store(sh + 2 * A_H, sh + 2 * A_H + B_H, r0 + 64, c0, vb1);
    __syncthreads();

    for (int s = 0; s < nstage; s++) {
        if (s + 1 < nstage) {
            const int k0 = (s + 1) * 16;
            va0 = *(const float4*)(Ap + (size_t)r0 * K + k0 + c0);
            va1 = *(const float4*)(Ap + (size_t)(r0 + 64) * K + k0 + c0);
            vb0 = *(const float4*)(Wp + (size_t)r0 * K + k0 + c0);
            vb1 = *(const float4*)(Wp + (size_t)(r0 + 64) * K + k0 + c0);
        }
        {
            const uint32_t base = smem_u32 + (unsigned)(s & 1) * (STAGE_H * 2);
            const uint32_t baseAhi = base;
            const uint32_t baseAlo = base + A_H * 2;
            const uint32_t baseBhi = base + 2 * A_H * 2;
            const uint32_t baseBlo = base + (2 * A_H + B_H) * 2;

            unsigned Bh[2][4], Bl[2][4];
#pragma unroll
            for (int anp = 0; anp < 2; anp++) {
                const uint32_t off = (uint32_t)(((warp_n * 32 + anp * 16 +
                                                  ((lane >> 4) & 1) * 8 + (lane & 7)) * GP +
                                                 ((lane >> 3) & 1) * 8) * 2);
                ldm_x4(Bh[anp], baseBhi + off);
                ldm_x4(Bl[anp], baseBlo + off);
            }
#pragma unroll
            for (int am = 0; am < 4; am++) {
                unsigned Ah[4], Al[4];
                const uint32_t off =
                    (uint32_t)(((warp_m * 64 + am * 16 + a_lrow) * GP + a_lcol) * 2);
                ldm_x4(Ah, baseAhi + off);
                ldm_x4(Al, baseAlo + off);
#pragma unroll
                for (int anp = 0; anp < 2; anp++) {
                    mma_bf16(acc[am][2 * anp],     Ah, &Bh[anp][0]);
                    mma_bf16(acc[am][2 * anp + 1], Ah, &Bh[anp][2]);
                    mma_bf16(acc[am][2 * anp],     Ah, &Bl[anp][0]);
                    mma_bf16(acc[am][2 * anp + 1], Ah, &Bl[anp][2]);
                    mma_bf16(acc[am][2 * anp],     Al, &Bh[anp][0]);
                    mma_bf16(acc[am][2 * anp + 1], Al, &Bh[anp][2]);
                }
            }
        }
        if (s + 1 < nstage) {
            unsigned short* st = sh + (unsigned)((s + 1) & 1) * STAGE_H;
            cvt_store(st,           st + A_H,           r0,      c0, va0);
            cvt_store(st,           st + A_H,           r0 + 64, c0, va1);
            cvt_store(st + 2 * A_H, st + 2 * A_H + B_H, r0,      c0, vb0);
            cvt_store(st + 2 * A_H, st + 2 * A_H + B_H, r0 + 64, c0, vb1);
            __syncthreads();
        }
    }

    // Epilogue (optionally fused RoPE on Q/K columns: pairs are (e0,e1)/(e2,e3))
    const int mbase = blockIdx.y * 128 + warp_m * 64 + (lane >> 2);
    const int nbase = blockIdx.x * 128 + warp_n * 32 + (lane & 3) * 2;
#pragma unroll
    for (int am = 0; am < 4; am++) {
#pragma unroll
        for (int an = 0; an < 4; an++) {
            const int r = mbase + am * 16;
            const int c = nbase + an * 8;
            float e0 = acc[am][an][0], e1 = acc[am][an][1];
            float e2 = acc[am][an][2], e3 = acc[am][an][3];
            if (do_rope && c < 2048) {
                // pair index within head; inv_freq = 10000^(-j/32)
                int j = (c & 63) >> 1;
                float invf = exp2f(-(float)j * 0.41524101186092029f);
                float f0 = (float)(r & (TT - 1)) * invf;
                float f1 = (float)((r + 8) & (TT - 1)) * invf;
                float s0, c0f, s1, c1f;
                sincosf(f0, &s0, &c0f);
                sincosf(f1, &s1, &c1f);
                float t0 = e0 * c0f - e1 * s0;
                float t1 = e0 * s0 + e1 * c0f;
                float t2 = e2 * c1f - e3 * s1;
                float t3 = e2 * s1 + e3 * c1f;
                e0 = t0; e1 = t1; e2 = t2; e3 = t3;
            }
            *(float2*)&Cout[(size_t)r * N + c]       = make_float2(e0, e1);
            *(float2*)&Cout[(size_t)(r + 8) * N + c] = make_float2(e2, e3);
        }
    }
}

// ---------------------------------------------------------------------------
// Tensor-core causal flash attention.
// CTA: 128 q-rows, 8 warps (16 rows/warp), 64-key tiles.
// Double-buffered K/V smem: ONE syncthreads per tile, LDGs hoistable into
// the previous tile's compute. Scale folded into Q; PV full 3-pass split.
// ---------------------------------------------------------------------------
#define GP2 72
// per-stage region offsets (halves); stage k at (k&1)*KV_STG
#define KV_STG 18432
#define KHI_O 0
#define KLO_O 4608
#define VHI_O 9216
#define VLO_O 13824
#define QHI_O 36864
#define QLO_O 46080
#define ATTN_SMEM_HALVES 55296
#define ATTN_SMEM_BYTES (ATTN_SMEM_HALVES * 2)   // 110592 B

__global__ __launch_bounds__(256, 2) void attn_mma()
{
    extern __shared__ unsigned short ash[];

    const int bh = blockIdx.y;
    const int b = bh >> 4;
    const int h = bh & 15;
    const int qtile = 15 - blockIdx.x;     // heavy tiles first
    const int q0 = qtile * 128;
    const int tid = threadIdx.x;
    const int wid = tid >> 5;
    const int lane = tid & 31;

    const float* base = g_qkv + (size_t)b * TT * C3;

    const uint32_t sm_u = (uint32_t)__cvta_generic_to_shared(ash);
    const uint32_t qh_u = sm_u + QHI_O * 2;
    const uint32_t ql_u = sm_u + QLO_O * 2;

    const int a_lrow = (lane & 7) + ((lane >> 3) & 1) * 8;
    const int a_lcol = ((lane >> 4) & 1) * 8;

    // ---- stage Q (128 x 64), scale 1/sqrt(64) folded in ----
#pragma unroll
    for (int it = 0; it < 8; it++) {
        int idx = tid + it * 256;               // 2048 float4 slots
        int r = idx >> 4, c4 = (idx & 15) * 4;
        float4 v = *(const float4*)(base + (size_t)(q0 + r) * C3 + h * HD + c4);
        v.x *= 0.125f; v.y *= 0.125f; v.z *= 0.125f; v.w *= 0.125f;
        uint2 hp, lp;
        split4(v, hp, lp);
        *(uint2*)&ash[QHI_O + r * GP2 + c4] = hp;
        *(uint2*)&ash[QLO_O + r * GP2 + c4] = lp;
    }
    // (no sync here: first loop iteration's sync covers Q visibility)

    // per-kk Q fragment smem offsets (fragments re-loaded each tile)
    uint32_t qoff[4];
#pragma unroll
    for (int kk = 0; kk < 4; kk++)
        qoff[kk] = (uint32_t)(((wid * 16 + a_lrow) * GP2 + kk * 16 + a_lcol) * 2);

    float o[8][4];
#pragma unroll
    for (int nb = 0; nb < 8; nb++)
#pragma unroll
        for (int e = 0; e < 4; e++) o[nb][e] = 0.f;
    float m0 = -1e30f, m1 = -1e30f, l0 = 0.f, l1 = 0.f;

    const int rg0 = q0 + wid * 16 + (lane >> 2);
    const int rg1 = rg0 + 8;
    const int cbase = (lane & 3) * 2;

    const int nkt = 2 * qtile + 2;
    for (int kt = 0; kt < nkt; kt++) {
        const int k0 = kt * 64;
        const unsigned stg = (unsigned)(kt & 1) * KV_STG;

        // ---- load K,V tile kt into buf(kt&1); other buf untouched ----
        // (LDGs independent of prior compute -> ptxas may hoist/overlap)
#pragma unroll
        for (int it = 0; it < 4; it++) {
            int idx = tid + it * 256;            // 1024 slots
            int r = idx >> 4, c4 = (idx & 15) * 4;
            const float* src = base + (size_t)(k0 + r) * C3 + CC + h * HD + c4;
            float4 kv = *(const float4*)src;
            float4 vv = *(const float4*)(src + CC);
            uint2 hp, lp;
            split4(kv, hp, lp);
            *(uint2*)&ash[stg + KHI_O + r * GP2 + c4] = hp;
            *(uint2*)&ash[stg + KLO_O + r * GP2 + c4] = lp;
            split4(vv, hp, lp);
            *(uint2*)&ash[stg + VHI_O + r * GP2 + c4] = hp;
            *(uint2*)&ash[stg + VLO_O + r * GP2 + c4] = lp;
        }
        __syncthreads();   // one barrier per tile

        const uint32_t kh_u = sm_u + (stg + KHI_O) * 2;
        const uint32_t kl_u = sm_u + (stg + KLO_O) * 2;
        const uint32_t vh_u = sm_u + (stg + VHI_O) * 2;
        const uint32_t vl_u = sm_u + (stg + VLO_O) * 2;

        // ---- S = Q K^T (3-pass split, x4 B loads, Q frags from smem) ----
        float s[8][4];
#pragma unroll
        for (int nb = 0; nb < 8; nb++)
#pragma unroll
            for (int e = 0; e < 4; e++) s[nb][e] = 0.f;

#pragma unroll
        for (int kk = 0; kk < 4; kk++) {
            unsigned Qh[4], Ql[4];
            ldm_x4(Qh, qh_u + qoff[kk]);
            ldm_x4(Ql, ql_u + qoff[kk]);
#pragma unroll
            for (int nbp = 0; nbp < 4; nbp++) {
                unsigned Bh[4], Bl[4];
                uint32_t off = (uint32_t)(((nbp * 16 + ((lane >> 4) & 1) * 8 + (lane & 7)) * GP2 +
                                           kk * 16 + ((lane >> 3) & 1) * 8) * 2);
                ldm_x4(Bh, kh_u + off);
                ldm_x4(Bl, kl_u + off);
                mma_bf16(s[2 * nbp],     Qh, &Bh[0]);
                mma_bf16(s[2 * nbp + 1], Qh, &Bh[2]);
                mma_bf16(s[2 * nbp],     Qh, &Bl[0]);
                mma_bf16(s[2 * nbp + 1], Qh, &Bl[2]);
                mma_bf16(s[2 * nbp],     Ql, &Bh[0]);
                mma_bf16(s[2 * nbp + 1], Ql, &Bh[2]);
            }
        }

        // ---- causal mask (scale already folded into Q) ----
        const bool diag = (kt >= 2 * qtile);
        if (diag) {
#pragma unroll
            for (int nb = 0; nb < 8; nb++) {
                int c0g = k0 + nb * 8 + cbase;
#pragma unroll
                for (int e = 0; e < 4; e++) {
                    int col = c0g + (e & 1);
                    int row = (e < 2) ? rg0 : rg1;
                    if (col > row) s[nb][e] = -1e30f;
                }
            }
        }

        // ---- online softmax ----
        float mx0 = -1e30f, mx1 = -1e30f;
#pragma unroll
        for (int nb = 0; nb < 8; nb++) {
            mx0 = fmaxf(mx0, fmaxf(s[nb][0], s[nb][1]));
            mx1 = fmaxf(mx1, fmaxf(s[nb][2], s[nb][3]));
        }
        mx0 = fmaxf(mx0, __shfl_xor_sync(0xffffffffu, mx0, 1));
        mx0 = fmaxf(mx0, __shfl_xor_sync(0xffffffffu, mx0, 2));
        mx1 = fmaxf(mx1, __shfl_xor_sync(0xffffffffu, mx1, 1));
        mx1 = fmaxf(mx1, __shfl_xor_sync(0xffffffffu, mx1, 2));

        float nm0 = fmaxf(m0, mx0), nm1 = fmaxf(m1, mx1);
        float corr0 = fexp(m0 - nm0), corr1 = fexp(m1 - nm1);
        m0 = nm0; m1 = nm1;

        float ls0 = 0.f, ls1 = 0.f;
#pragma unroll
        for (int nb = 0; nb < 8; nb++) {
            s[nb][0] = fexp(s[nb][0] - nm0); ls0 += s[nb][0];
            s[nb][1] = fexp(s[nb][1] - nm0); ls0 += s[nb][1];
            s[nb][2] = fexp(s[nb][2] - nm1); ls1 += s[nb][2];
            s[nb][3] = fexp(s[nb][3] - nm1); ls1 += s[nb][3];
        }
        ls0 += __shfl_xor_sync(0xffffffffu, ls0, 1);
        ls0 += __shfl_xor_sync(0xffffffffu, ls0, 2);
        ls1 += __shfl_xor_sync(0xffffffffu, ls1, 1);
        ls1 += __shfl_xor_sync(0xffffffffu, ls1, 2);
        l0 = l0 * corr0 + ls0;
        l1 = l1 * corr1 + ls1;

#pragma unroll
        for (int nb = 0; nb < 8; nb++) {
            o[nb][0] *= corr0; o[nb][1] *= corr0;
            o[nb][2] *= corr1; o[nb][3] *= corr1;
        }

        // ---- O += P V (3-pass split, x4 trans B loads) ----
#pragma unroll
        for (int kc = 0; kc < 4; kc++) {
            unsigned ah[4], al[4];
            {
                float* p0 = s[2 * kc];
                float* p1 = s[2 * kc + 1];
                ah[0] = pack2bf(p0[0], p0[1]);
                ah[1] = pack2bf(p0[2], p0[3]);
                ah[2] = pack2bf(p1[0], p1[1]);
                ah[3] = pack2bf(p1[2], p1[3]);
                al[0] = pack2bf(p0[0] - bflo(ah[0]), p0[1] - bfhi(ah[0]));
                al[1] = pack2bf(p0[2] - bflo(ah[1]), p0[3] - bfhi(ah[1]));
                al[2] = pack2bf(p1[0] - bflo(ah[2]), p1[1] - bfhi(ah[2]));
                al[3] = pack2bf(p1[2] - bflo(ah[3]), p1[3] - bfhi(ah[3]));
            }
#pragma unroll
            for (int nbp = 0; nbp < 4; nbp++) {
                unsigned Bh[4], Bl[4];
                uint32_t off = (uint32_t)(((kc * 16 + (lane & 15)) * GP2 +
                                           (nbp * 2 + ((lane >> 4) & 1)) * 8) * 2);
                ldm_x4t(Bh, vh_u + off);
                ldm_x4t(Bl, vl_u + off);
                mma_bf16(o[2 * nbp],     ah, &Bh[0]);
                mma_bf16(o[2 * nbp + 1], ah, &Bh[2]);
                mma_bf16(o[2 * nbp],     ah, &Bl[0]);
                mma_bf16(o[2 * nbp + 1], ah, &Bl[2]);
                mma_bf16(o[2 * nbp],     al, &Bh[0]);
                mma_bf16(o[2 * nbp + 1], al, &Bh[2]);
            }
        }
    }

    // ---- epilogue ----
    const float i0 = 1.f / l0, i1 = 1.f / l1;
    float* out0 = g_attn + (size_t)(b * TT + rg0) * CC + h * HD + cbase;
    float* out1 = g_attn + (size_t)(b * TT + rg1) * CC + h * HD + cbase;
#pragma unroll
    for (int nb = 0; nb < 8; nb++) {
        *(float2*)(out0 + nb * 8) = make_float2(o[nb][0] * i0, o[nb][1] * i0);
        *(float2*)(out1 + nb * 8) = make_float2(o[nb][2] * i1, o[nb][3] * i1);
    }
}

// ---------------------------------------------------------------------------
extern "C" void kernel_launch(void* const* d_in, const int* in_sizes, int n_in,
                              void* d_out, int out_size)
{
    const float* x     = (const float*)d_in[0];   // (4096,1024)
    const float* w_qkv = (const float*)d_in[1];   // (3072,1024)
    const float* w_out = (const float*)d_in[2];   // (1024,1024)
    float* out = (float*)d_out;                   // (4096,1024)

    float* qkv;  cudaGetSymbolAddress((void**)&qkv,  g_qkv);
    float* attn; cudaGetSymbolAddress((void**)&attn, g_attn);

    const int M = BB * TT;

    static int attr_set = 0;
    if (!attr_set) {
        cudaFuncSetAttribute(gemm_bf16x3,
                             cudaFuncAttributeMaxDynamicSharedMemorySize,
                             GEMM_SMEM_BYTES);
        cudaFuncSetAttribute(attn_mma,
                             cudaFuncAttributeMaxDynamicSharedMemorySize,
                             ATTN_SMEM_BYTES);
        attr_set = 1;
    }

    // 1) qkv = x @ w_qkv^T with fused RoPE on Q/K columns
    gemm_bf16x3<<<dim3(C3 / 128, M / 128), 256, GEMM_SMEM_BYTES>>>(x, w_qkv, qkv, M, C3, CC, 1);

    // 2) attention
    attn_mma<<<dim3(TT / 128, BB * HH), 256, ATTN_SMEM_BYTES>>>();

    // 3) out = attn @ w_out^T
    gemm_bf16x3<<<dim3(CC / 128, M / 128), 256, GEMM_SMEM_BYTES>>>(attn, w_out, out, M, CC, CC, 0);
}

// round 16
// speedup vs baseline: 1.4742x; 1.2887x over previous
#include <cuda_runtime.h>
#include <cuda_fp16.h>
#include <math.h>
#include <stdint.h>

#define BB 2
#define TT 2048
#define CC 1024
#define HH 16
#define HD 64
#define C3 3072

__device__ float g_qkv[(size_t)BB * TT * C3];   // 4096 x 3072
__device__ float g_attn[(size_t)BB * TT * CC];  // 4096 x 1024

// ---------------------------------------------------------------------------
// mma / ldmatrix helpers (fp16)
// ---------------------------------------------------------------------------
__device__ __forceinline__ void mma_f16(float* c, const unsigned* a, const unsigned* b) {
    asm("mma.sync.aligned.m16n8k16.row.col.f32.f16.f16.f32 "
        "{%0,%1,%2,%3},{%4,%5,%6,%7},{%8,%9},{%0,%1,%2,%3};"
        : "+f"(c[0]), "+f"(c[1]), "+f"(c[2]), "+f"(c[3])
        : "r"(a[0]), "r"(a[1]), "r"(a[2]), "r"(a[3]), "r"(b[0]), "r"(b[1]));
}
__device__ __forceinline__ void ldm_x4(unsigned* r, uint32_t addr) {
    asm volatile("ldmatrix.sync.aligned.m8n8.x4.shared.b16 {%0,%1,%2,%3}, [%4];"
                 : "=r"(r[0]), "=r"(r[1]), "=r"(r[2]), "=r"(r[3]) : "r"(addr));
}
__device__ __forceinline__ void ldm_x4t(unsigned* r, uint32_t addr) {
    asm volatile("ldmatrix.sync.aligned.m8n8.x4.trans.shared.b16 {%0,%1,%2,%3}, [%4];"
                 : "=r"(r[0]), "=r"(r[1]), "=r"(r[2]), "=r"(r[3]) : "r"(addr));
}

// pack two fp32 -> f16x2 (lo in low half)
__device__ __forceinline__ unsigned pack2hf(float lo, float hi) {
    unsigned r;
    asm("cvt.rn.f16x2.f32 %0, %1, %2;" : "=r"(r) : "f"(hi), "f"(lo));
    return r;
}
__device__ __forceinline__ float2 unpackhf(unsigned u) {
    __half2 h = *reinterpret_cast<__half2*>(&u);
    return __half22float2(h);
}

// fast exp on fma/alu pipes (no MUFU)
__device__ __forceinline__ float fexp(float x) {
    float y = x * 1.4426950408889634f;
    y = fmaxf(y, -126.0f);
    int ni = __float2int_rd(y);
    float f = y - (float)ni;
    float p = 0.0018775767f;
    p = fmaf(p, f, 0.0089893397f);
    p = fmaf(p, f, 0.0558282185f);
    p = fmaf(p, f, 0.2400789568f);
    p = fmaf(p, f, 0.6931531203f);
    p = fmaf(p, f, 0.9999999702f);
    return __uint_as_float(__float_as_uint(p) + ((unsigned)ni << 23));
}

// split float4 -> f16 hi pair + f16 residual pair
__device__ __forceinline__ void split4h(float4 v, uint2& hp, uint2& lp) {
    unsigned h01 = pack2hf(v.x, v.y);
    unsigned h23 = pack2hf(v.z, v.w);
    float2 f01 = unpackhf(h01);
    float2 f23 = unpackhf(h23);
    hp = make_uint2(h01, h23);
    lp = make_uint2(pack2hf(v.x - f01.x, v.y - f01.y),
                    pack2hf(v.z - f23.x, v.w - f23.y));
}
// hi-only convert
__device__ __forceinline__ uint2 cvt4h(float4 v) {
    return make_uint2(pack2hf(v.x, v.y), pack2hf(v.z, v.w));
}

// ---------------------------------------------------------------------------
// Tensor-core GEMM (NT), fp16 2-pass split: A hi-only, B hi+lo.
// CTA 128x128, BK=16, 256 threads (8 warps, 2x4), warp tile 64x32, 2 CTAs/SM.
// Optional fused RoPE epilogue.
// ---------------------------------------------------------------------------
#define GP 24
#define A_H (128 * GP)                  // 3072 halves (A hi)
#define B_H (128 * GP)                  // 3072 halves (per B tile)
#define STAGE_H (A_H + 2 * B_H)         // 9216 halves
#define GEMM_SMEM_BYTES (2 * STAGE_H * 2)   // 36864 B

__device__ __forceinline__ void cvt_store_hl(unsigned short* hi_t, unsigned short* lo_t,
                                             int row, int col, float4 v) {
    uint2 hp, lp;
    split4h(v, hp, lp);
    *(uint2*)&hi_t[row * GP + col] = hp;
    *(uint2*)&lo_t[row * GP + col] = lp;
}
__device__ __forceinline__ void cvt_store_hi(unsigned short* t, int row, int col, float4 v) {
    *(uint2*)&t[row * GP + col] = cvt4h(v);
}

__global__ __launch_bounds__(256, 2) void gemm_f16x2(
    const float* __restrict__ A, const float* __restrict__ W,
    float* __restrict__ Cout, int M, int N, int K, int do_rope)
{
    extern __shared__ unsigned short sh[];

    const int tid = threadIdx.x;
    const int wid = tid >> 5;
    const int lane = tid & 31;
    const int warp_m = wid >> 2;        // 0..1 -> 64-row slices of 128
    const int warp_n = wid & 3;         // 0..3 -> 32-col slices of 128

    const float* Ap = A + (size_t)blockIdx.y * 128 * K;
    const float* Wp = W + (size_t)blockIdx.x * 128 * K;

    const int r0 = tid >> 2;
    const int c0 = (tid & 3) * 4;

    const uint32_t smem_u32 = (uint32_t)__cvta_generic_to_shared(sh);

    const int a_lrow = (lane & 7) + ((lane >> 3) & 1) * 8;
    const int a_lcol = ((lane >> 4) & 1) * 8;

    float acc[4][4][4];
#pragma unroll
    for (int i = 0; i < 4; i++)
#pragma unroll
        for (int j = 0; j < 4; j++)
#pragma unroll
            for (int q = 0; q < 4; q++) acc[i][j][q] = 0.f;

    const int nstage = K / 16;

    float4 va0 = *(const float4*)(Ap + (size_t)r0 * K + c0);
    float4 va1 = *(const float4*)(Ap + (size_t)(r0 + 64) * K + c0);
    float4 vb0 = *(const float4*)(Wp + (size_t)r0 * K + c0);
    float4 vb1 = *(const float4*)(Wp + (size_t)(r0 + 64) * K + c0);
    cvt_store_hi(sh, r0,      c0, va0);
    cvt_store_hi(sh, r0 + 64, c0, va1);
    cvt_store_hl(sh + A_H, sh + A_H + B_H, r0,      c0, vb0);
    cvt_store_hl(sh + A_H, sh + A_H + B_H, r0 + 64, c0, vb1);
    __syncthreads();

    for (int s = 0; s < nstage; s++) {
        if (s + 1 < nstage) {
            const int k0 = (s + 1) * 16;
            va0 = *(const float4*)(Ap + (size_t)r0 * K + k0 + c0);
            va1 = *(const float4*)(Ap + (size_t)(r0 + 64) * K + k0 + c0);
            vb0 = *(const float4*)(Wp + (size_t)r0 * K + k0 + c0);
            vb1 = *(const float4*)(Wp + (size_t)(r0 + 64) * K + k0 + c0);
        }
        {
            const uint32_t base = smem_u32 + (unsigned)(s & 1) * (STAGE_H * 2);
            const uint32_t baseAhi = base;
            const uint32_t baseBhi = base + A_H * 2;
            const uint32_t baseBlo = base + (A_H + B_H) * 2;

            unsigned Bh[2][4], Bl[2][4];
#pragma unroll
            for (int anp = 0; anp < 2; anp++) {
                const uint32_t off = (uint32_t)(((warp_n * 32 + anp * 16 +
                                                  ((lane >> 4) & 1) * 8 + (lane & 7)) * GP +
                                                 ((lane >> 3) & 1) * 8) * 2);
                ldm_x4(Bh[anp], baseBhi + off);
                ldm_x4(Bl[anp], baseBlo + off);
            }
#pragma unroll
            for (int am = 0; am < 4; am++) {
                unsigned Ah[4];
                const uint32_t off =
                    (uint32_t)(((warp_m * 64 + am * 16 + a_lrow) * GP + a_lcol) * 2);
                ldm_x4(Ah, baseAhi + off);
#pragma unroll
                for (int anp = 0; anp < 2; anp++) {
                    mma_f16(acc[am][2 * anp],     Ah, &Bh[anp][0]);
                    mma_f16(acc[am][2 * anp + 1], Ah, &Bh[anp][2]);
                    mma_f16(acc[am][2 * anp],     Ah, &Bl[anp][0]);
                    mma_f16(acc[am][2 * anp + 1], Ah, &Bl[anp][2]);
                }
            }
        }
        if (s + 1 < nstage) {
            unsigned short* st = sh + (unsigned)((s + 1) & 1) * STAGE_H;
            cvt_store_hi(st, r0,      c0, va0);
            cvt_store_hi(st, r0 + 64, c0, va1);
            cvt_store_hl(st + A_H, st + A_H + B_H, r0,      c0, vb0);
            cvt_store_hl(st + A_H, st + A_H + B_H, r0 + 64, c0, vb1);
            __syncthreads();
        }
    }

    // Epilogue (optionally fused RoPE on Q/K columns: pairs are (e0,e1)/(e2,e3))
    const int mbase = blockIdx.y * 128 + warp_m * 64 + (lane >> 2);
    const int nbase = blockIdx.x * 128 + warp_n * 32 + (lane & 3) * 2;
#pragma unroll
    for (int am = 0; am < 4; am++) {
#pragma unroll
        for (int an = 0; an < 4; an++) {
            const int r = mbase + am * 16;
            const int c = nbase + an * 8;
            float e0 = acc[am][an][0], e1 = acc[am][an][1];
            float e2 = acc[am][an][2], e3 = acc[am][an][3];
            if (do_rope && c < 2048) {
                int j = (c & 63) >> 1;
                float invf = exp2f(-(float)j * 0.41524101186092029f);
                float f0 = (float)(r & (TT - 1)) * invf;
                float f1 = (float)((r + 8) & (TT - 1)) * invf;
                float s0, c0f, s1, c1f;
                sincosf(f0, &s0, &c0f);
                sincosf(f1, &s1, &c1f);
                float t0 = e0 * c0f - e1 * s0;
                float t1 = e0 * s0 + e1 * c0f;
                float t2 = e2 * c1f - e3 * s1;
                float t3 = e2 * s1 + e3 * c1f;
                e0 = t0; e1 = t1; e2 = t2; e3 = t3;
            }
            *(float2*)&Cout[(size_t)r * N + c]       = make_float2(e0, e1);
            *(float2*)&Cout[(size_t)(r + 8) * N + c] = make_float2(e2, e3);
        }
    }
}

// ---------------------------------------------------------------------------
// Tensor-core causal flash attention, fp16 2-pass split.
// CTA: 128 q-rows, 8 warps (16 rows/warp), 64-key tiles, double-buffered K/V.
// Q hi-only (scale folded); K,V hi+lo; P hi-only.
// ---------------------------------------------------------------------------
#define GP2 72
#define KV_STG 18432
#define KHI_O 0
#define KLO_O 4608
#define VHI_O 9216
#define VLO_O 13824
#define QHI_O 36864
// Q region: 128 rows * GP2 = 9216 halves -> total 46080 halves
#define ATTN_SMEM_HALVES 46080
#define ATTN_SMEM_BYTES (ATTN_SMEM_HALVES * 2)   // 92160 B

__global__ __launch_bounds__(256, 2) void attn_mma()
{
    extern __shared__ unsigned short ash[];

    const int bh = blockIdx.y;
    const int b = bh >> 4;
    const int h = bh & 15;
    const int qtile = 15 - blockIdx.x;     // heavy tiles first
    const int q0 = qtile * 128;
    const int tid = threadIdx.x;
    const int wid = tid >> 5;
    const int lane = tid & 31;

    const float* base = g_qkv + (size_t)b * TT * C3;

    const uint32_t sm_u = (uint32_t)__cvta_generic_to_shared(ash);
    const uint32_t qh_u = sm_u + QHI_O * 2;

    const int a_lrow = (lane & 7) + ((lane >> 3) & 1) * 8;
    const int a_lcol = ((lane >> 4) & 1) * 8;

    // ---- stage Q (128 x 64) hi-only, scale 1/sqrt(64) folded in ----
#pragma unroll
    for (int it = 0; it < 8; it++) {
        int idx = tid + it * 256;               // 2048 float4 slots
        int r = idx >> 4, c4 = (idx & 15) * 4;
        float4 v = *(const float4*)(base + (size_t)(q0 + r) * C3 + h * HD + c4);
        v.x *= 0.125f; v.y *= 0.125f; v.z *= 0.125f; v.w *= 0.125f;
        *(uint2*)&ash[QHI_O + r * GP2 + c4] = cvt4h(v);
    }
    // (first loop iteration's sync covers Q visibility)

    uint32_t qoff[4];
#pragma unroll
    for (int kk = 0; kk < 4; kk++)
        qoff[kk] = (uint32_t)(((wid * 16 + a_lrow) * GP2 + kk * 16 + a_lcol) * 2);

    float o[8][4];
#pragma unroll
    for (int nb = 0; nb < 8; nb++)
#pragma unroll
        for (int e = 0; e < 4; e++) o[nb][e] = 0.f;
    float m0 = -1e30f, m1 = -1e30f, l0 = 0.f, l1 = 0.f;

    const int rg0 = q0 + wid * 16 + (lane >> 2);
    const int rg1 = rg0 + 8;
    const int cbase = (lane & 3) * 2;

    const int nkt = 2 * qtile + 2;
    for (int kt = 0; kt < nkt; kt++) {
        const int k0 = kt * 64;
        const unsigned stg = (unsigned)(kt & 1) * KV_STG;

        // ---- load K,V tile kt into buf(kt&1), split f16 hi/lo ----
#pragma unroll
        for (int it = 0; it < 4; it++) {
            int idx = tid + it * 256;            // 1024 slots
            int r = idx >> 4, c4 = (idx & 15) * 4;
            const float* src = base + (size_t)(k0 + r) * C3 + CC + h * HD + c4;
            float4 kv = *(const float4*)src;
            float4 vv = *(const float4*)(src + CC);
            uint2 hp, lp;
            split4h(kv, hp, lp);
            *(uint2*)&ash[stg + KHI_O + r * GP2 + c4] = hp;
            *(uint2*)&ash[stg + KLO_O + r * GP2 + c4] = lp;
            split4h(vv, hp, lp);
            *(uint2*)&ash[stg + VHI_O + r * GP2 + c4] = hp;
            *(uint2*)&ash[stg + VLO_O + r * GP2 + c4] = lp;
        }
        __syncthreads();

        const uint32_t kh_u = sm_u + (stg + KHI_O) * 2;
        const uint32_t kl_u = sm_u + (stg + KLO_O) * 2;
        const uint32_t vh_u = sm_u + (stg + VHI_O) * 2;
        const uint32_t vl_u = sm_u + (stg + VLO_O) * 2;

        // ---- S = Q K^T (2-pass: Qh x Kh + Qh x Kl) ----
        float s[8][4];
#pragma unroll
        for (int nb = 0; nb < 8; nb++)
#pragma unroll
            for (int e = 0; e < 4; e++) s[nb][e] = 0.f;

#pragma unroll
        for (int kk = 0; kk < 4; kk++) {
            unsigned Qh[4];
            ldm_x4(Qh, qh_u + qoff[kk]);
#pragma unroll
            for (int nbp = 0; nbp < 4; nbp++) {
                unsigned Bh[4], Bl[4];
                uint32_t off = (uint32_t)(((nbp * 16 + ((lane >> 4) & 1) * 8 + (lane & 7)) * GP2 +
                                           kk * 16 + ((lane >> 3) & 1) * 8) * 2);
                ldm_x4(Bh, kh_u + off);
                ldm_x4(Bl, kl_u + off);
                mma_f16(s[2 * nbp],     Qh, &Bh[0]);
                mma_f16(s[2 * nbp + 1], Qh, &Bh[2]);
                mma_f16(s[2 * nbp],     Qh, &Bl[0]);
                mma_f16(s[2 * nbp + 1], Qh, &Bl[2]);
            }
        }

        // ---- causal mask ----
        const bool diag = (kt >= 2 * qtile);
        if (diag) {
#pragma unroll
            for (int nb = 0; nb < 8; nb++) {
                int c0g = k0 + nb * 8 + cbase;
#pragma unroll
                for (int e = 0; e < 4; e++) {
                    int col = c0g + (e & 1);
                    int row = (e < 2) ? rg0 : rg1;
                    if (col > row) s[nb][e] = -1e30f;
                }
            }
        }

        // ---- online softmax ----
        float mx0 = -1e30f, mx1 = -1e30f;
#pragma unroll
        for (int nb = 0; nb < 8; nb++) {
            mx0 = fmaxf(mx0, fmaxf(s[nb][0], s[nb][1]));
            mx1 = fmaxf(mx1, fmaxf(s[nb][2], s[nb][3]));
        }
        mx0 = fmaxf(mx0, __shfl_xor_sync(0xffffffffu, mx0, 1));
        mx0 = fmaxf(mx0, __shfl_xor_sync(0xffffffffu, mx0, 2));
        mx1 = fmaxf(mx1, __shfl_xor_sync(0xffffffffu, mx1, 1));
        mx1 = fmaxf(mx1, __shfl_xor_sync(0xffffffffu, mx1, 2));

        float nm0 = fmaxf(m0, mx0), nm1 = fmaxf(m1, mx1);
        float corr0 = fexp(m0 - nm0), corr1 = fexp(m1 - nm1);
        m0 = nm0; m1 = nm1;

        float ls0 = 0.f, ls1 = 0.f;
#pragma unroll
        for (int nb = 0; nb < 8; nb++) {
            s[nb][0] = fexp(s[nb][0] - nm0); ls0 += s[nb][0];
            s[nb][1] = fexp(s[nb][1] - nm0); ls0 += s[nb][1];
            s[nb][2] = fexp(s[nb][2] - nm1); ls1 += s[nb][2];
            s[nb][3] = fexp(s[nb][3] - nm1); ls1 += s[nb][3];
        }
        ls0 += __shfl_xor_sync(0xffffffffu, ls0, 1);
        ls0 += __shfl_xor_sync(0xffffffffu, ls0, 2);
        ls1 += __shfl_xor_sync(0xffffffffu, ls1, 1);
        ls1 += __shfl_xor_sync(0xffffffffu, ls1, 2);
        l0 = l0 * corr0 + ls0;
        l1 = l1 * corr1 + ls1;

#pragma unroll
        for (int nb = 0; nb < 8; nb++) {
            o[nb][0] *= corr0; o[nb][1] *= corr0;
            o[nb][2] *= corr1; o[nb][3] *= corr1;
        }

        // ---- O += P V (2-pass: Ph x Vh + Ph x Vl) ----
#pragma unroll
        for (int kc = 0; kc < 4; kc++) {
            unsigned ah[4];
            {
                float* p0 = s[2 * kc];
                float* p1 = s[2 * kc + 1];
                ah[0] = pack2hf(p0[0], p0[1]);
                ah[1] = pack2hf(p0[2], p0[3]);
                ah[2] = pack2hf(p1[0], p1[1]);
                ah[3] = pack2hf(p1[2], p1[3]);
            }
#pragma unroll
            for (int nbp = 0; nbp < 4; nbp++) {
                unsigned Bh[4], Bl[4];
                uint32_t off = (uint32_t)(((kc * 16 + (lane & 15)) * GP2 +
                                           (nbp * 2 + ((lane >> 4) & 1)) * 8) * 2);
                ldm_x4t(Bh, vh_u + off);
                ldm_x4t(Bl, vl_u + off);
                mma_f16(o[2 * nbp],     ah, &Bh[0]);
                mma_f16(o[2 * nbp + 1], ah, &Bh[2]);
                mma_f16(o[2 * nbp],     ah, &Bl[0]);
                mma_f16(o[2 * nbp + 1], ah, &Bl[2]);
            }
        }
    }

    // ---- epilogue ----
    const float i0 = 1.f / l0, i1 = 1.f / l1;
    float* out0 = g_attn + (size_t)(b * TT + rg0) * CC + h * HD + cbase;
    float* out1 = g_attn + (size_t)(b * TT + rg1) * CC + h * HD + cbase;
#pragma unroll
    for (int nb = 0; nb < 8; nb++) {
        *(float2*)(out0 + nb * 8) = make_float2(o[nb][0] * i0, o[nb][1] * i0);
        *(float2*)(out1 + nb * 8) = make_float2(o[nb][2] * i1, o[nb][3] * i1);
    }
}

// ---------------------------------------------------------------------------
extern "C" void kernel_launch(void* const* d_in, const int* in_sizes, int n_in,
                              void* d_out, int out_size)
{
    const float* x     = (const float*)d_in[0];   // (4096,1024)
    const float* w_qkv = (const float*)d_in[1];   // (3072,1024)
    const float* w_out = (const float*)d_in[2];   // (1024,1024)
    float* out = (float*)d_out;                   // (4096,1024)

    float* qkv;  cudaGetSymbolAddress((void**)&qkv,  g_qkv);
    float* attn; cudaGetSymbolAddress((void**)&attn, g_attn);

    const int M = BB * TT;

    static int attr_set = 0;
    if (!attr_set) {
        cudaFuncSetAttribute(gemm_f16x2,
                             cudaFuncAttributeMaxDynamicSharedMemorySize,
                             GEMM_SMEM_BYTES);
        cudaFuncSetAttribute(attn_mma,
                             cudaFuncAttributeMaxDynamicSharedMemorySize,
                             ATTN_SMEM_BYTES);
        attr_set = 1;
    }

    // 1) qkv = x @ w_qkv^T with fused RoPE on Q/K columns
    gemm_f16x2<<<dim3(C3 / 128, M / 128), 256, GEMM_SMEM_BYTES>>>(x, w_qkv, qkv, M, C3, CC, 1);

    // 2) attention
    attn_mma<<<dim3(TT / 128, BB * HH), 256, ATTN_SMEM_BYTES>>>();

    // 3) out = attn @ w_out^T
    gemm_f16x2<<<dim3(CC / 128, M / 128), 256, GEMM_SMEM_BYTES>>>(attn, w_out, out, M, CC, CC, 0);
}

// round 17
// speedup vs baseline: 1.7808x; 1.2080x over previous
#include <cuda_runtime.h>
#include <cuda_fp16.h>
#include <math.h>
#include <stdint.h>

#define BB 2
#define TT 2048
#define CC 1024
#define HH 16
#define HD 64
#define C3 3072

__device__ float g_qkv[(size_t)BB * TT * C3];   // 4096 x 3072
__device__ float g_attn[(size_t)BB * TT * CC];  // 4096 x 1024

// ---------------------------------------------------------------------------
// mma / ldmatrix helpers (fp16)
// ---------------------------------------------------------------------------
__device__ __forceinline__ void mma_f16(float* c, const unsigned* a, const unsigned* b) {
    asm("mma.sync.aligned.m16n8k16.row.col.f32.f16.f16.f32 "
        "{%0,%1,%2,%3},{%4,%5,%6,%7},{%8,%9},{%0,%1,%2,%3};"
        : "+f"(c[0]), "+f"(c[1]), "+f"(c[2]), "+f"(c[3])
        : "r"(a[0]), "r"(a[1]), "r"(a[2]), "r"(a[3]), "r"(b[0]), "r"(b[1]));
}
__device__ __forceinline__ void ldm_x4(unsigned* r, uint32_t addr) {
    asm volatile("ldmatrix.sync.aligned.m8n8.x4.shared.b16 {%0,%1,%2,%3}, [%4];"
                 : "=r"(r[0]), "=r"(r[1]), "=r"(r[2]), "=r"(r[3]) : "r"(addr));
}
__device__ __forceinline__ void ldm_x4t(unsigned* r, uint32_t addr) {
    asm volatile("ldmatrix.sync.aligned.m8n8.x4.trans.shared.b16 {%0,%1,%2,%3}, [%4];"
                 : "=r"(r[0]), "=r"(r[1]), "=r"(r[2]), "=r"(r[3]) : "r"(addr));
}

// pack two fp32 -> f16x2 (lo in low half)
__device__ __forceinline__ unsigned pack2hf(float lo, float hi) {
    unsigned r;
    asm("cvt.rn.f16x2.f32 %0, %1, %2;" : "=r"(r) : "f"(hi), "f"(lo));
    return r;
}
__device__ __forceinline__ float2 unpackhf(unsigned u) {
    __half2 h = *reinterpret_cast<__half2*>(&u);
    return __half22float2(h);
}

// fast exp on fma/alu pipes (no MUFU)
__device__ __forceinline__ float fexp(float x) {
    float y = x * 1.4426950408889634f;
    y = fmaxf(y, -126.0f);
    int ni = __float2int_rd(y);
    float f = y - (float)ni;
    float p = 0.0018775767f;
    p = fmaf(p, f, 0.0089893397f);
    p = fmaf(p, f, 0.0558282185f);
    p = fmaf(p, f, 0.2400789568f);
    p = fmaf(p, f, 0.6931531203f);
    p = fmaf(p, f, 0.9999999702f);
    return __uint_as_float(__float_as_uint(p) + ((unsigned)ni << 23));
}

// split float4 -> f16 hi pair + f16 residual pair
__device__ __forceinline__ void split4h(float4 v, uint2& hp, uint2& lp) {
    unsigned h01 = pack2hf(v.x, v.y);
    unsigned h23 = pack2hf(v.z, v.w);
    float2 f01 = unpackhf(h01);
    float2 f23 = unpackhf(h23);
    hp = make_uint2(h01, h23);
    lp = make_uint2(pack2hf(v.x - f01.x, v.y - f01.y),
                    pack2hf(v.z - f23.x, v.w - f23.y));
}
// hi-only convert
__device__ __forceinline__ uint2 cvt4h(float4 v) {
    return make_uint2(pack2hf(v.x, v.y), pack2hf(v.z, v.w));
}

// ---------------------------------------------------------------------------
// Tensor-core GEMM (NT), pure fp16 single-pass (A hi, B hi).
// CTA 128x128, BK=16, 256 threads (8 warps, 2x4), warp tile 64x32, 2 CTAs/SM.
// Optional fused RoPE epilogue.
// ---------------------------------------------------------------------------
#define GP 24
#define A_H (128 * GP)                  // 3072 halves (A hi)
#define B_H (128 * GP)                  // 3072 halves (B hi)
#define STAGE_H (A_H + B_H)             // 6144 halves
#define GEMM_SMEM_BYTES (2 * STAGE_H * 2)   // 24576 B

__device__ __forceinline__ void cvt_store_hi(unsigned short* t, int row, int col, float4 v) {
    *(uint2*)&t[row * GP + col] = cvt4h(v);
}

__global__ __launch_bounds__(256, 2) void gemm_f16(
    const float* __restrict__ A, const float* __restrict__ W,
    float* __restrict__ Cout, int M, int N, int K, int do_rope)
{
    extern __shared__ unsigned short sh[];

    const int tid = threadIdx.x;
    const int wid = tid >> 5;
    const int lane = tid & 31;
    const int warp_m = wid >> 2;        // 0..1 -> 64-row slices of 128
    const int warp_n = wid & 3;         // 0..3 -> 32-col slices of 128

    const float* Ap = A + (size_t)blockIdx.y * 128 * K;
    const float* Wp = W + (size_t)blockIdx.x * 128 * K;

    const int r0 = tid >> 2;
    const int c0 = (tid & 3) * 4;

    const uint32_t smem_u32 = (uint32_t)__cvta_generic_to_shared(sh);

    const int a_lrow = (lane & 7) + ((lane >> 3) & 1) * 8;
    const int a_lcol = ((lane >> 4) & 1) * 8;

    float acc[4][4][4];
#pragma unroll
    for (int i = 0; i < 4; i++)
#pragma unroll
        for (int j = 0; j < 4; j++)
#pragma unroll
            for (int q = 0; q < 4; q++) acc[i][j][q] = 0.f;

    const int nstage = K / 16;

    float4 va0 = *(const float4*)(Ap + (size_t)r0 * K + c0);
    float4 va1 = *(const float4*)(Ap + (size_t)(r0 + 64) * K + c0);
    float4 vb0 = *(const float4*)(Wp + (size_t)r0 * K + c0);
    float4 vb1 = *(const float4*)(Wp + (size_t)(r0 + 64) * K + c0);
    cvt_store_hi(sh, r0,      c0, va0);
    cvt_store_hi(sh, r0 + 64, c0, va1);
    cvt_store_hi(sh + A_H, r0,      c0, vb0);
    cvt_store_hi(sh + A_H, r0 + 64, c0, vb1);
    __syncthreads();

    for (int s = 0; s < nstage; s++) {
        if (s + 1 < nstage) {
            const int k0 = (s + 1) * 16;
            va0 = *(const float4*)(Ap + (size_t)r0 * K + k0 + c0);
            va1 = *(const float4*)(Ap + (size_t)(r0 + 64) * K + k0 + c0);
            vb0 = *(const float4*)(Wp + (size_t)r0 * K + k0 + c0);
            vb1 = *(const float4*)(Wp + (size_t)(r0 + 64) * K + k0 + c0);
        }
        {
            const uint32_t base = smem_u32 + (unsigned)(s & 1) * (STAGE_H * 2);
            const uint32_t baseAhi = base;
            const uint32_t baseBhi = base + A_H * 2;

            unsigned Bh[2][4];
#pragma unroll
            for (int anp = 0; anp < 2; anp++) {
                const uint32_t off = (uint32_t)(((warp_n * 32 + anp * 16 +
                                                  ((lane >> 4) & 1) * 8 + (lane & 7)) * GP +
                                                 ((lane >> 3) & 1) * 8) * 2);
                ldm_x4(Bh[anp], baseBhi + off);
            }
#pragma unroll
            for (int am = 0; am < 4; am++) {
                unsigned Ah[4];
                const uint32_t off =
                    (uint32_t)(((warp_m * 64 + am * 16 + a_lrow) * GP + a_lcol) * 2);
                ldm_x4(Ah, baseAhi + off);
#pragma unroll
                for (int anp = 0; anp < 2; anp++) {
                    mma_f16(acc[am][2 * anp],     Ah, &Bh[anp][0]);
                    mma_f16(acc[am][2 * anp + 1], Ah, &Bh[anp][2]);
                }
            }
        }
        if (s + 1 < nstage) {
            unsigned short* st = sh + (unsigned)((s + 1) & 1) * STAGE_H;
            cvt_store_hi(st, r0,      c0, va0);
            cvt_store_hi(st, r0 + 64, c0, va1);
            cvt_store_hi(st + A_H, r0,      c0, vb0);
            cvt_store_hi(st + A_H, r0 + 64, c0, vb1);
            __syncthreads();
        }
    }

    // Epilogue (optionally fused RoPE on Q/K columns: pairs are (e0,e1)/(e2,e3))
    const int mbase = blockIdx.y * 128 + warp_m * 64 + (lane >> 2);
    const int nbase = blockIdx.x * 128 + warp_n * 32 + (lane & 3) * 2;
#pragma unroll
    for (int am = 0; am < 4; am++) {
#pragma unroll
        for (int an = 0; an < 4; an++) {
            const int r = mbase + am * 16;
            const int c = nbase + an * 8;
            float e0 = acc[am][an][0], e1 = acc[am][an][1];
            float e2 = acc[am][an][2], e3 = acc[am][an][3];
            if (do_rope && c < 2048) {
                int j = (c & 63) >> 1;
                float invf = exp2f(-(float)j * 0.41524101186092029f);
                float f0 = (float)(r & (TT - 1)) * invf;
                float f1 = (float)((r + 8) & (TT - 1)) * invf;
                float s0, c0f, s1, c1f;
                sincosf(f0, &s0, &c0f);
                sincosf(f1, &s1, &c1f);
                float t0 = e0 * c0f - e1 * s0;
                float t1 = e0 * s0 + e1 * c0f;
                float t2 = e2 * c1f - e3 * s1;
                float t3 = e2 * s1 + e3 * c1f;
                e0 = t0; e1 = t1; e2 = t2; e3 = t3;
            }
            *(float2*)&Cout[(size_t)r * N + c]       = make_float2(e0, e1);
            *(float2*)&Cout[(size_t)(r + 8) * N + c] = make_float2(e2, e3);
        }
    }
}

// ---------------------------------------------------------------------------
// Tensor-core causal flash attention, fp16.
// CTA: 128 q-rows, 8 warps (16 rows/warp), 64-key tiles, double-buffered K/V.
// Q hi-only (scale folded); K hi+lo (exponent-sensitive); V hi-only; P hi-only.
// ---------------------------------------------------------------------------
#define GP2 72
#define KV_STG 13824
#define KHI_O 0
#define KLO_O 4608
#define VHI_O 9216
#define QHI_O 27648
// Q region: 128 rows * GP2 = 9216 halves -> total 36864 halves
#define ATTN_SMEM_HALVES 36864
#define ATTN_SMEM_BYTES (ATTN_SMEM_HALVES * 2)   // 73728 B

__global__ __launch_bounds__(256, 2) void attn_mma()
{
    extern __shared__ unsigned short ash[];

    const int bh = blockIdx.y;
    const int b = bh >> 4;
    const int h = bh & 15;
    const int qtile = 15 - blockIdx.x;     // heavy tiles first
    const int q0 = qtile * 128;
    const int tid = threadIdx.x;
    const int wid = tid >> 5;
    const int lane = tid & 31;

    const float* base = g_qkv + (size_t)b * TT * C3;

    const uint32_t sm_u = (uint32_t)__cvta_generic_to_shared(ash);
    const uint32_t qh_u = sm_u + QHI_O * 2;

    const int a_lrow = (lane & 7) + ((lane >> 3) & 1) * 8;
    const int a_lcol = ((lane >> 4) & 1) * 8;

    // ---- stage Q (128 x 64) hi-only, scale 1/sqrt(64) folded in ----
#pragma unroll
    for (int it = 0; it < 8; it++) {
        int idx = tid + it * 256;               // 2048 float4 slots
        int r = idx >> 4, c4 = (idx & 15) * 4;
        float4 v = *(const float4*)(base + (size_t)(q0 + r) * C3 + h * HD + c4);
        v.x *= 0.125f; v.y *= 0.125f; v.z *= 0.125f; v.w *= 0.125f;
        *(uint2*)&ash[QHI_O + r * GP2 + c4] = cvt4h(v);
    }
    // (first loop iteration's sync covers Q visibility)

    uint32_t qoff[4];
#pragma unroll
    for (int kk = 0; kk < 4; kk++)
        qoff[kk] = (uint32_t)(((wid * 16 + a_lrow) * GP2 + kk * 16 + a_lcol) * 2);

    float o[8][4];
#pragma unroll
    for (int nb = 0; nb < 8; nb++)
#pragma unroll
        for (int e = 0; e < 4; e++) o[nb][e] = 0.f;
    float m0 = -1e30f, m1 = -1e30f, l0 = 0.f, l1 = 0.f;

    const int rg0 = q0 + wid * 16 + (lane >> 2);
    const int rg1 = rg0 + 8;
    const int cbase = (lane & 3) * 2;

    const int nkt = 2 * qtile + 2;
    for (int kt = 0; kt < nkt; kt++) {
        const int k0 = kt * 64;
        const unsigned stg = (unsigned)(kt & 1) * KV_STG;

        // ---- load K,V tile kt into buf(kt&1): K split hi/lo, V hi ----
#pragma unroll
        for (int it = 0; it < 4; it++) {
            int idx = tid + it * 256;            // 1024 slots
            int r = idx >> 4, c4 = (idx & 15) * 4;
            const float* src = base + (size_t)(k0 + r) * C3 + CC + h * HD + c4;
            float4 kv = *(const float4*)src;
            float4 vv = *(const float4*)(src + CC);
            uint2 hp, lp;
            split4h(kv, hp, lp);
            *(uint2*)&ash[stg + KHI_O + r * GP2 + c4] = hp;
            *(uint2*)&ash[stg + KLO_O + r * GP2 + c4] = lp;
            *(uint2*)&ash[stg + VHI_O + r * GP2 + c4] = cvt4h(vv);
        }
        __syncthreads();

        const uint32_t kh_u = sm_u + (stg + KHI_O) * 2;
        const uint32_t kl_u = sm_u + (stg + KLO_O) * 2;
        const uint32_t vh_u = sm_u + (stg + VHI_O) * 2;

        // ---- S = Q K^T (2-pass: Qh x Kh + Qh x Kl) ----
        float s[8][4];
#pragma unroll
        for (int nb = 0; nb < 8; nb++)
#pragma unroll
            for (int e = 0; e < 4; e++) s[nb][e] = 0.f;

#pragma unroll
        for (int kk = 0; kk < 4; kk++) {
            unsigned Qh[4];
            ldm_x4(Qh, qh_u + qoff[kk]);
#pragma unroll
            for (int nbp = 0; nbp < 4; nbp++) {
                unsigned Bh[4], Bl[4];
                uint32_t off = (uint32_t)(((nbp * 16 + ((lane >> 4) & 1) * 8 + (lane & 7)) * GP2 +
                                           kk * 16 + ((lane >> 3) & 1) * 8) * 2);
                ldm_x4(Bh, kh_u + off);
                ldm_x4(Bl, kl_u + off);
                mma_f16(s[2 * nbp],     Qh, &Bh[0]);
                mma_f16(s[2 * nbp + 1], Qh, &Bh[2]);
                mma_f16(s[2 * nbp],     Qh, &Bl[0]);
                mma_f16(s[2 * nbp + 1], Qh, &Bl[2]);
            }
        }

        // ---- causal mask ----
        const bool diag = (kt >= 2 * qtile);
        if (diag) {
#pragma unroll
            for (int nb = 0; nb < 8; nb++) {
                int c0g = k0 + nb * 8 + cbase;
#pragma unroll
                for (int e = 0; e < 4; e++) {
                    int col = c0g + (e & 1);
                    int row = (e < 2) ? rg0 : rg1;
                    if (col > row) s[nb][e] = -1e30f;
                }
            }
        }

        // ---- online softmax ----
        float mx0 = -1e30f, mx1 = -1e30f;
#pragma unroll
        for (int nb = 0; nb < 8; nb++) {
            mx0 = fmaxf(mx0, fmaxf(s[nb][0], s[nb][1]));
            mx1 = fmaxf(mx1, fmaxf(s[nb][2], s[nb][3]));
        }
        mx0 = fmaxf(mx0, __shfl_xor_sync(0xffffffffu, mx0, 1));
        mx0 = fmaxf(mx0, __shfl_xor_sync(0xffffffffu, mx0, 2));
        mx1 = fmaxf(mx1, __shfl_xor_sync(0xffffffffu, mx1, 1));
        mx1 = fmaxf(mx1, __shfl_xor_sync(0xffffffffu, mx1, 2));

        float nm0 = fmaxf(m0, mx0), nm1 = fmaxf(m1, mx1);
        float corr0 = fexp(m0 - nm0), corr1 = fexp(m1 - nm1);
        m0 = nm0; m1 = nm1;

        float ls0 = 0.f, ls1 = 0.f;
#pragma unroll
        for (int nb = 0; nb < 8; nb++) {
            s[nb][0] = fexp(s[nb][0] - nm0); ls0 += s[nb][0];
            s[nb][1] = fexp(s[nb][1] - nm0); ls0 += s[nb][1];
            s[nb][2] = fexp(s[nb][2] - nm1); ls1 += s[nb][2];
            s[nb][3] = fexp(s[nb][3] - nm1); ls1 += s[nb][3];
        }
        ls0 += __shfl_xor_sync(0xffffffffu, ls0, 1);
        ls0 += __shfl_xor_sync(0xffffffffu, ls0, 2);
        ls1 += __shfl_xor_sync(0xffffffffu, ls1, 1);
        ls1 += __shfl_xor_sync(0xffffffffu, ls1, 2);
        l0 = l0 * corr0 + ls0;
        l1 = l1 * corr1 + ls1;

#pragma unroll
        for (int nb = 0; nb < 8; nb++) {
            o[nb][0] *= corr0; o[nb][1] *= corr0;
            o[nb][2] *= corr1; o[nb][3] *= corr1;
        }

        // ---- O += P V (single pass: Ph x Vh) ----
#pragma unroll
        for (int kc = 0; kc < 4; kc++) {
            unsigned ah[4];
            {
                float* p0 = s[2 * kc];
                float* p1 = s[2 * kc + 1];
                ah[0] = pack2hf(p0[0], p0[1]);
                ah[1] = pack2hf(p0[2], p0[3]);
                ah[2] = pack2hf(p1[0], p1[1]);
                ah[3] = pack2hf(p1[2], p1[3]);
            }
#pragma unroll
            for (int nbp = 0; nbp < 4; nbp++) {
                unsigned Bh[4];
                uint32_t off = (uint32_t)(((kc * 16 + (lane & 15)) * GP2 +
                                           (nbp * 2 + ((lane >> 4) & 1)) * 8) * 2);
                ldm_x4t(Bh, vh_u + off);
                mma_f16(o[2 * nbp],     ah, &Bh[0]);
                mma_f16(o[2 * nbp + 1], ah, &Bh[2]);
            }
        }
    }

    // ---- epilogue ----
    const float i0 = 1.f / l0, i1 = 1.f / l1;
    float* out0 = g_attn + (size_t)(b * TT + rg0) * CC + h * HD + cbase;
    float* out1 = g_attn + (size_t)(b * TT + rg1) * CC + h * HD + cbase;
#pragma unroll
    for (int nb = 0; nb < 8; nb++) {
        *(float2*)(out0 + nb * 8) = make_float2(o[nb][0] * i0, o[nb][1] * i0);
        *(float2*)(out1 + nb * 8) = make_float2(o[nb][2] * i1, o[nb][3] * i1);
    }
}

// ---------------------------------------------------------------------------
extern "C" void kernel_launch(void* const* d_in, const int* in_sizes, int n_in,
                              void* d_out, int out_size)
{
    const float* x     = (const float*)d_in[0];   // (4096,1024)
    const float* w_qkv = (const float*)d_in[1];   // (3072,1024)
    const float* w_out = (const float*)d_in[2];   // (1024,1024)
    float* out = (float*)d_out;                   // (4096,1024)

    float* qkv;  cudaGetSymbolAddress((void**)&qkv,  g_qkv);
    float* attn; cudaGetSymbolAddress((void**)&attn, g_attn);

    const int M = BB * TT;

    static int attr_set = 0;
    if (!attr_set) {
        cudaFuncSetAttribute(gemm_f16,
                             cudaFuncAttributeMaxDynamicSharedMemorySize,
                             GEMM_SMEM_BYTES);
        cudaFuncSetAttribute(attn_mma,
                             cudaFuncAttributeMaxDynamicSharedMemorySize,
                             ATTN_SMEM_BYTES);
        attr_set = 1;
    }

    // 1) qkv = x @ w_qkv^T with fused RoPE on Q/K columns
    gemm_f16<<<dim3(C3 / 128, M / 128), 256, GEMM_SMEM_BYTES>>>(x, w_qkv, qkv, M, C3, CC, 1);

    // 2) attention
    attn_mma<<<dim3(TT / 128, BB * HH), 256, ATTN_SMEM_BYTES>>>();

    // 3) out = attn @ w_out^T
    gemm_f16<<<dim3(CC / 128, M / 128), 256, GEMM_SMEM_BYTES>>>(attn, w_out, out, M, CC, CC, 0);
}